// round 5
// baseline (speedup 1.0000x reference)
#include <cuda_runtime.h>
#include <cuda_bf16.h>
#include <math.h>
#include <stdint.h>

// ---------------- problem constants ----------------
#define Bb 4
#define Cc 256
#define Hh 80
#define Ww 80
#define Nq 300
#define IDim 128
#define HID 512
#define H2 160
#define W2 160
#define HW (Hh*Ww)
#define CHW (Cc*HW)

// ---------------- device scratch (f32) ----------------
__device__ float g_x[Bb*CHW];      // block0 output
__device__ float g_y[Bb*CHW];      // block1 output (final spatial)
__device__ float g_t[Bb*CHW];      // dw temp (pre-LN)
__device__ float g_mean[Bb*HW];
__device__ float g_inv[Bb*HW];
__device__ float g_q1[Bb*Nq*HID];
__device__ float g_q2[Bb*Nq*HID];
__device__ float g_q4[Bb*Nq*IDim];
__device__ float g_qq[Bb*Nq*Cc];
__device__ float g_off[Bb*Nq];
__device__ float g_m[Bb*Nq*HW];    // mask at 80x80

// ---------------- device scratch (bf16 hi/lo splits) ----------------
__device__ __nv_bfloat16 g_bth[Bb*HW*Cc], g_btl[Bb*HW*Cc];  // spatial B [pix x C], reused
__device__ __nv_bfloat16 g_pwh[2*Cc*Cc],  g_pwl[2*Cc*Cc];
__device__ __nv_bfloat16 g_w1h[HID*Cc],   g_w1l[HID*Cc];
__device__ __nv_bfloat16 g_w2h[HID*HID],  g_w2l[HID*HID];
__device__ __nv_bfloat16 g_w3h[Cc*HID],   g_w3l[Cc*HID];
__device__ __nv_bfloat16 g_qph[IDim*Cc],  g_qpl[IDim*Cc];
__device__ __nv_bfloat16 g_sph[Cc*IDim],  g_spl[Cc*IDim];   // sproj transposed
__device__ __nv_bfloat16 g_ah[Bb*Nq*HID], g_al[Bb*Nq*HID];  // activation split, reused

__device__ __forceinline__ float gelu_f(float x) {
    return 0.5f * x * (1.0f + erff(x * 0.70710678118654752f));
}
__device__ __forceinline__ uint32_t su32(const void* p) {
    return (uint32_t)__cvta_generic_to_shared(p);
}
__device__ __forceinline__ void ldsm4(uint32_t* r, uint32_t addr) {
    asm volatile("ldmatrix.sync.aligned.m8n8.x4.shared.b16 {%0,%1,%2,%3}, [%4];"
        : "=r"(r[0]), "=r"(r[1]), "=r"(r[2]), "=r"(r[3]) : "r"(addr));
}
__device__ __forceinline__ void ldsm2(uint32_t* r, uint32_t addr) {
    asm volatile("ldmatrix.sync.aligned.m8n8.x2.shared.b16 {%0,%1}, [%2];"
        : "=r"(r[0]), "=r"(r[1]) : "r"(addr));
}
__device__ __forceinline__ void mma16816(float* d, const uint32_t* a, const uint32_t* b) {
    asm volatile("mma.sync.aligned.m16n8k16.row.col.f32.bf16.bf16.f32 "
        "{%0,%1,%2,%3}, {%4,%5,%6,%7}, {%8,%9}, {%0,%1,%2,%3};"
        : "+f"(d[0]), "+f"(d[1]), "+f"(d[2]), "+f"(d[3])
        : "r"(a[0]), "r"(a[1]), "r"(a[2]), "r"(a[3]), "r"(b[0]), "r"(b[1]));
}
__device__ __forceinline__ void split_bf16(float x, __nv_bfloat16& hi, __nv_bfloat16& lo) {
    hi = __float2bfloat16(x);
    lo = __float2bfloat16(x - __bfloat162float(hi));
}
__device__ __forceinline__ void cpa16(uint32_t d, const void* s, int bytes) {
    asm volatile("cp.async.cg.shared.global [%0], [%1], 16, %2;"
        :: "r"(d), "l"(s), "r"(bytes));
}
#define CP_COMMIT asm volatile("cp.async.commit_group;")
#define CP_WAIT0  asm volatile("cp.async.wait_group 0;")

// ---------------- depthwise 3x3 conv (SAME) + bias ----------------
__global__ void dw_kernel(const float* __restrict__ x, const float* __restrict__ w,
                          const float* __restrict__ bia, float* __restrict__ out)
{
    int wq = threadIdx.x;
    int hq = blockIdx.y * 4 + threadIdx.y;
    int plane = blockIdx.z;
    int c = plane & (Cc - 1);
    const float* xp = x + (long)plane * HW;
    const float* wp = w + c * 9;
    float w00 = wp[0], w01 = wp[1], w02 = wp[2];
    float w10 = wp[3], w11 = wp[4], w12 = wp[5];
    float w20 = wp[6], w21 = wp[7], w22 = wp[8];
    float acc = bia[c];

    const float* r0 = xp + (hq - 1) * Ww;
    const float* r1 = xp + hq * Ww;
    const float* r2 = xp + (hq + 1) * Ww;
    bool ht = hq > 0, hb = hq < Hh - 1;
    bool wl = wq > 0, wr = wq < Ww - 1;

    if (ht) {
        if (wl) acc += w00 * r0[wq - 1];
        acc += w01 * r0[wq];
        if (wr) acc += w02 * r0[wq + 1];
    }
    {
        if (wl) acc += w10 * r1[wq - 1];
        acc += w11 * r1[wq];
        if (wr) acc += w12 * r1[wq + 1];
    }
    if (hb) {
        if (wl) acc += w20 * r2[wq - 1];
        acc += w21 * r2[wq];
        if (wr) acc += w22 * r2[wq + 1];
    }
    out[(long)plane * HW + hq * Ww + wq] = acc;
}

// ---------------- LN stats per pixel ----------------
__global__ void stats_kernel(const float* __restrict__ t,
                             float* __restrict__ mean, float* __restrict__ inv)
{
    int p = blockIdx.x * blockDim.x + threadIdx.x;
    if (p >= Bb*HW) return;
    int bb = p / HW;
    int pix = p - bb * HW;
    const float* base = t + (long)bb * CHW + pix;
    float s = 0.f, s2 = 0.f;
#pragma unroll 8
    for (int c = 0; c < Cc; c++) {
        float v = base[(long)c * HW];
        s += v; s2 += v * v;
    }
    float m = s * (1.0f / Cc);
    float var = s2 * (1.0f / Cc) - m * m;
    mean[p] = m;
    inv[p] = rsqrtf(var + 1e-6f);
}

// ---------------- elementwise split f32 -> bf16 hi/lo ----------------
__global__ void split_k(const float* __restrict__ src,
                        __nv_bfloat16* __restrict__ hi, __nv_bfloat16* __restrict__ lo,
                        int n4)
{
    int i = blockIdx.x * blockDim.x + threadIdx.x;
    if (i >= n4) return;
    float4 v = ((const float4*)src)[i];
    __nv_bfloat16 h0,l0,h1,l1,h2,l2,h3,l3;
    split_bf16(v.x,h0,l0); split_bf16(v.y,h1,l1);
    split_bf16(v.z,h2,l2); split_bf16(v.w,h3,l3);
    ((__nv_bfloat162*)hi)[i*2]   = __nv_bfloat162(h0,h1);
    ((__nv_bfloat162*)hi)[i*2+1] = __nv_bfloat162(h2,h3);
    ((__nv_bfloat162*)lo)[i*2]   = __nv_bfloat162(l0,l1);
    ((__nv_bfloat162*)lo)[i*2+1] = __nv_bfloat162(l2,l3);
}

// ---------------- transpose + (optional LN) + split ----------------
// X: [Krows x Ncols] (per batch), O: [Ncols x Krows] bf16 hi/lo.
template<bool LNF>
__global__ void splitT_k(const float* __restrict__ X,
                         __nv_bfloat16* __restrict__ Oh, __nv_bfloat16* __restrict__ Ol,
                         const float* __restrict__ mean, const float* __restrict__ inv,
                         const float* __restrict__ lw, const float* __restrict__ lb,
                         int Krows, int Ncols)
{
    int z = blockIdx.z;
    long zoff = (long)z * Krows * Ncols;
    X += zoff; Oh += zoff; Ol += zoff;

    __shared__ float ts[32][33];
    int n0 = blockIdx.x * 32, k0 = blockIdx.y * 32;
    int tx = threadIdx.x, ty = threadIdx.y;   // (32, 8)

#pragma unroll
    for (int j = 0; j < 4; j++)
        ts[ty + j*8][tx] = X[(long)(k0 + ty + j*8) * Ncols + n0 + tx];
    __syncthreads();

#pragma unroll
    for (int j = 0; j < 4; j++) {
        int n = n0 + ty + j*8;
        int k = k0 + tx;
        float v = ts[tx][ty + j*8];
        if (LNF) {
            long mi = (long)z * Ncols + n;
            v = (v - mean[mi]) * inv[mi] * lw[k] + lb[k];
        }
        __nv_bfloat16 h, l;
        split_bf16(v, h, l);
        Oh[(long)n * Krows + k] = h;
        Ol[(long)n * Krows + k] = l;
    }
}

// ---------------- bf16 tensor-core GEMM, pre-split inputs ----------------
// C[m,n] = act( sum_k A[m,k]*B[n,k] + bias ) (+resid)
// A: [M x K] hi/lo, B: [N x K] hi/lo, both K-major bf16.
// BM=128, BN=128, BK=16. 8 warps (2m x 4n), warp tile 64x32.
// cp.async double-buffered. 3 passes: Ah*Bh + Ah*Bl + Al*Bh.
#define PADK 24

template<int ACT, int BIASM, bool RES>
__global__ void __launch_bounds__(256)
gemm_bf(const __nv_bfloat16* __restrict__ Ah, const __nv_bfloat16* __restrict__ Al,
        const __nv_bfloat16* __restrict__ Bh, const __nv_bfloat16* __restrict__ Bl,
        const float* __restrict__ bias, const float* __restrict__ resid,
        float* __restrict__ C, int M, int N, int K,
        long sA, long sB, long sC)
{
    int z = blockIdx.z;
    Ah += z * sA; Al += z * sA; Bh += z * sB; Bl += z * sB; C += z * sC;
    const float* R = RES ? (resid + z * sC) : nullptr;

    int m0 = blockIdx.y * 128;
    int n0 = blockIdx.x * 128;

    __shared__ __align__(16) __nv_bfloat16 As[2][2][128 * PADK];
    __shared__ __align__(16) __nv_bfloat16 Bs[2][2][128 * PADK];

    int tid = threadIdx.x;
    int warp = tid >> 5;
    int lane = tid & 31;
    int wm = warp >> 2;       // 0..1 -> m offset 64*wm
    int wn = warp & 3;        // 0..3 -> n offset 32*wn

    // loader: each thread does one 16B chunk per matrix per stage
    int ar = tid >> 1;            // 0..127
    int ac = (tid & 1) * 8;       // 0 or 8 (bf16 elems)
    bool mok = (m0 + ar) < M;
    int abytes = mok ? 16 : 0;
    const __nv_bfloat16* Ahp = Ah + (long)(m0 + ar) * K + ac;
    const __nv_bfloat16* Alp = Al + (long)(m0 + ar) * K + ac;
    const __nv_bfloat16* Bhp = Bh + (long)(n0 + ar) * K + ac;
    const __nv_bfloat16* Blp = Bl + (long)(n0 + ar) * K + ac;

    uint32_t dA = su32(&As[0][0][ar * PADK + ac]);
    uint32_t dB = su32(&Bs[0][0][ar * PADK + ac]);
    const uint32_t BUFST = 2 * 128 * PADK;   // bytes between buf0/buf1 (elems*2 = 128*PADK*2*... )
    const uint32_t SPLST = 128 * PADK * 2;   // bytes between hi/lo planes

    float acc[4][4][4];
#pragma unroll
    for (int i = 0; i < 4; i++)
#pragma unroll
        for (int j = 0; j < 4; j++)
#pragma unroll
            for (int q = 0; q < 4; q++) acc[i][j][q] = 0.f;

    const int KT = K >> 4;

    // prologue: stage 0
    {
        cpa16(dA,         Ahp, abytes);
        cpa16(dA + SPLST, Alp, abytes);
        cpa16(dB,         Bhp, 16);
        cpa16(dB + SPLST, Blp, 16);
        CP_COMMIT;
        CP_WAIT0;
    }
    __syncthreads();

    int a_mrow = lane & 15;
    int a_kh = (lane >> 4) * 8;
    int b_nrow = lane & 7;
    int b_kh = ((lane >> 3) & 1) * 8;

    for (int kt = 0; kt < KT; kt++) {
        int buf = kt & 1;
        if (kt + 1 < KT) {
            int off = (kt + 1) << 4;
            uint32_t d2A = dA + (buf ^ 1) * (BUFST * 2);  // careful: BUFST in elems? -> compute in bytes below
            // recompute in bytes: buf stride = 2 planes * 128*PADK elems * 2B
            d2A = dA + (uint32_t)((buf ^ 1) * 2 * 128 * PADK * 2);
            uint32_t d2B = dB + (uint32_t)((buf ^ 1) * 2 * 128 * PADK * 2);
            cpa16(d2A,         Ahp + off, abytes);
            cpa16(d2A + SPLST, Alp + off, abytes);
            cpa16(d2B,         Bhp + off, 16);
            cpa16(d2B + SPLST, Blp + off, 16);
            CP_COMMIT;
        }

        // compute on buf
        uint32_t afr[2][4][4];
        uint32_t bfr[2][4][2];
#pragma unroll
        for (int s = 0; s < 2; s++) {
#pragma unroll
            for (int mt = 0; mt < 4; mt++) {
                uint32_t addr = su32(&As[buf][s][(wm*64 + mt*16 + a_mrow) * PADK + a_kh]);
                ldsm4(afr[s][mt], addr);
            }
#pragma unroll
            for (int nt = 0; nt < 4; nt++) {
                uint32_t addr = su32(&Bs[buf][s][(wn*32 + nt*8 + b_nrow) * PADK + b_kh]);
                ldsm2(bfr[s][nt], addr);
            }
        }
#pragma unroll
        for (int mt = 0; mt < 4; mt++)
#pragma unroll
            for (int nt = 0; nt < 4; nt++) {
                mma16816(acc[mt][nt], afr[0][mt], bfr[0][nt]);  // hi*hi
                mma16816(acc[mt][nt], afr[0][mt], bfr[1][nt]);  // hi*lo
                mma16816(acc[mt][nt], afr[1][mt], bfr[0][nt]);  // lo*hi
            }

        if (kt + 1 < KT) {
            CP_WAIT0;
            __syncthreads();
        }
    }

    // ---- epilogue ----
#pragma unroll
    for (int mt = 0; mt < 4; mt++) {
#pragma unroll
        for (int nt = 0; nt < 4; nt++) {
            int gn = n0 + wn*32 + nt*8 + (lane & 3) * 2;
            float bn0v = 0.f, bn1v = 0.f;
            if (BIASM == 2) { bn0v = bias[gn]; bn1v = bias[gn + 1]; }
#pragma unroll
            for (int h = 0; h < 2; h++) {
                int row = m0 + wm*64 + mt*16 + (lane >> 2) + h*8;
                if (row >= M) continue;
                float x0 = acc[mt][nt][h*2 + 0];
                float x1 = acc[mt][nt][h*2 + 1];
                if (BIASM == 1) { float bm = bias[row]; x0 += bm; x1 += bm; }
                if (BIASM == 2) { x0 += bn0v; x1 += bn1v; }
                if (ACT == 1) { x0 = fmaxf(x0, 0.f); x1 = fmaxf(x1, 0.f); }
                if (ACT == 2) { x0 = gelu_f(x0); x1 = gelu_f(x1); }
                if (RES) {
                    float2 r2 = *(const float2*)&R[(long)row * N + gn];
                    x0 += r2.x; x1 += r2.y;
                }
                float2 o; o.x = x0; o.y = x1;
                *(float2*)&C[(long)row * N + gn] = o;
            }
        }
    }
}

// ---------------- per-query offset ----------------
__global__ void off_kernel(const float* __restrict__ q4, const float* __restrict__ sb,
                           const float* __restrict__ hb, float* __restrict__ off)
{
    int n = blockIdx.x * blockDim.x + threadIdx.x;
    if (n >= Bb*Nq) return;
    float s = hb[0];
#pragma unroll 8
    for (int i = 0; i < IDim; i++) s += q4[(long)n * IDim + i] * sb[i];
    off[n] = s;
}

// ---------------- bilinear 2x upsample + offset ----------------
__global__ void upsample_kernel(const float* __restrict__ m, const float* __restrict__ off,
                                float* __restrict__ out)
{
    long idx = (long)blockIdx.x * blockDim.x + threadIdx.x;
    const long tot4 = (long)Bb * Nq * H2 * (W2 / 4);
    if (idx >= tot4) return;
    int wq4 = (int)(idx % (W2 / 4)) * 4;
    int h2 = (int)((idx / (W2 / 4)) % H2);
    long bn = idx / ((long)(W2 / 4) * H2);

    float fh = h2 * 0.5f - 0.25f;
    int h0f = (int)floorf(fh);
    float wh = fh - (float)h0f;
    int h0 = max(h0f, 0), h1 = min(h0f + 1, Hh - 1);

    const float* r0 = m + bn * (long)HW + h0 * Ww;
    const float* r1 = m + bn * (long)HW + h1 * Ww;
    float o = off[bn];

    float r[4];
#pragma unroll
    for (int j = 0; j < 4; j++) {
        int w2 = wq4 + j;
        float fw = w2 * 0.5f - 0.25f;
        int w0f = (int)floorf(fw);
        float ww = fw - (float)w0f;
        int w0 = max(w0f, 0), w1 = min(w0f + 1, Ww - 1);
        float t0 = r0[w0] * (1.f - ww) + r0[w1] * ww;
        float t1 = r1[w0] * (1.f - ww) + r1[w1] * ww;
        r[j] = t0 * (1.f - wh) + t1 * wh + o;
    }
    float4 v = make_float4(r[0], r[1], r[2], r[3]);
    *(float4*)(out + bn * (long)(H2 * W2) + (long)h2 * W2 + wq4) = v;
}

// ---------------- launcher ----------------
extern "C" void kernel_launch(void* const* d_in, const int* in_sizes, int n_in,
                              void* d_out, int out_size)
{
    const float* spat    = (const float*)d_in[0];
    const float* qf      = (const float*)d_in[1];
    const float* dw_w    = (const float*)d_in[2];
    const float* dw_b    = (const float*)d_in[3];
    const float* ln_w    = (const float*)d_in[4];
    const float* ln_b    = (const float*)d_in[5];
    const float* pw_w    = (const float*)d_in[6];
    const float* pw_b    = (const float*)d_in[7];
    const float* sproj_w = (const float*)d_in[8];
    const float* sproj_b = (const float*)d_in[9];
    const float* mlp_w1  = (const float*)d_in[10];
    const float* mlp_b1  = (const float*)d_in[11];
    const float* mlp_w2  = (const float*)d_in[12];
    const float* mlp_b2  = (const float*)d_in[13];
    const float* mlp_w3  = (const float*)d_in[14];
    const float* mlp_b3  = (const float*)d_in[15];
    const float* qproj_w = (const float*)d_in[16];
    const float* qproj_b = (const float*)d_in[17];
    const float* head_b  = (const float*)d_in[18];
    float* out = (float*)d_out;

    float *px, *py, *pt, *pmean, *pinv, *pq1, *pq2, *pq4, *pqq, *poff, *pm;
    cudaGetSymbolAddress((void**)&px,    g_x);
    cudaGetSymbolAddress((void**)&py,    g_y);
    cudaGetSymbolAddress((void**)&pt,    g_t);
    cudaGetSymbolAddress((void**)&pmean, g_mean);
    cudaGetSymbolAddress((void**)&pinv,  g_inv);
    cudaGetSymbolAddress((void**)&pq1,   g_q1);
    cudaGetSymbolAddress((void**)&pq2,   g_q2);
    cudaGetSymbolAddress((void**)&pq4,   g_q4);
    cudaGetSymbolAddress((void**)&pqq,   g_qq);
    cudaGetSymbolAddress((void**)&poff,  g_off);
    cudaGetSymbolAddress((void**)&pm,    g_m);

    __nv_bfloat16 *bth,*btl,*pwh,*pwl,*w1h,*w1l,*w2h,*w2l,*w3h,*w3l,*qph,*qpl,*sph,*spl,*ah,*al;
    cudaGetSymbolAddress((void**)&bth, g_bth);
    cudaGetSymbolAddress((void**)&btl, g_btl);
    cudaGetSymbolAddress((void**)&pwh, g_pwh);
    cudaGetSymbolAddress((void**)&pwl, g_pwl);
    cudaGetSymbolAddress((void**)&w1h, g_w1h);
    cudaGetSymbolAddress((void**)&w1l, g_w1l);
    cudaGetSymbolAddress((void**)&w2h, g_w2h);
    cudaGetSymbolAddress((void**)&w2l, g_w2l);
    cudaGetSymbolAddress((void**)&w3h, g_w3h);
    cudaGetSymbolAddress((void**)&w3l, g_w3l);
    cudaGetSymbolAddress((void**)&qph, g_qph);
    cudaGetSymbolAddress((void**)&qpl, g_qpl);
    cudaGetSymbolAddress((void**)&sph, g_sph);
    cudaGetSymbolAddress((void**)&spl, g_spl);
    cudaGetSymbolAddress((void**)&ah,  g_ah);
    cudaGetSymbolAddress((void**)&al,  g_al);

    dim3 dwBlock(80, 4);
    dim3 dwGrid(1, Hh / 4, Bb * Cc);
    dim3 tBlock(32, 8);
    const int pix = Bb * HW;
    const int Mq = Bb * Nq;

    // ---- weight splits (independent) ----
    split_k<<<(2*Cc*Cc/4 + 255)/256, 256>>>(pw_w, pwh, pwl, 2*Cc*Cc/4);
    split_k<<<(HID*Cc/4 + 255)/256, 256>>>(mlp_w1, w1h, w1l, HID*Cc/4);
    split_k<<<(HID*HID/4 + 255)/256, 256>>>(mlp_w2, w2h, w2l, HID*HID/4);
    split_k<<<(Cc*HID/4 + 255)/256, 256>>>(mlp_w3, w3h, w3l, Cc*HID/4);
    split_k<<<(IDim*Cc/4 + 255)/256, 256>>>(qproj_w, qph, qpl, IDim*Cc/4);
    splitT_k<false><<<dim3(Cc/32, IDim/32, 1), tBlock>>>(
        sproj_w, sph, spl, nullptr, nullptr, nullptr, nullptr, IDim, Cc);

    // ---- spatial block 0 ----
    dw_kernel<<<dwGrid, dwBlock>>>(spat, dw_w, dw_b, pt);
    stats_kernel<<<(pix + 255)/256, 256>>>(pt, pmean, pinv);
    splitT_k<true><<<dim3(HW/32, Cc/32, Bb), tBlock>>>(
        pt, bth, btl, pmean, pinv, ln_w, ln_b, Cc, HW);
    gemm_bf<2, 1, true><<<dim3(HW/128, 2, Bb), 256>>>(
        pwh, pwl, bth, btl, pw_b, spat, px,
        Cc, HW, Cc, 0, (long)HW*Cc, (long)CHW);

    // ---- spatial block 1 ----
    dw_kernel<<<dwGrid, dwBlock>>>(px, dw_w + Cc*9, dw_b + Cc, pt);
    stats_kernel<<<(pix + 255)/256, 256>>>(pt, pmean, pinv);
    splitT_k<true><<<dim3(HW/32, Cc/32, Bb), tBlock>>>(
        pt, bth, btl, pmean, pinv, ln_w + Cc, ln_b + Cc, Cc, HW);
    gemm_bf<2, 1, true><<<dim3(HW/128, 2, Bb), 256>>>(
        pwh + Cc*Cc, pwl + Cc*Cc, bth, btl, pw_b + Cc, px, py,
        Cc, HW, Cc, 0, (long)HW*Cc, (long)CHW);

    // ---- query MLP chain (M = 1200) ----
    split_k<<<(Mq*Cc/4 + 255)/256, 256>>>(qf, ah, al, Mq*Cc/4);
    gemm_bf<1, 2, false><<<dim3(HID/128, 10, 1), 256>>>(
        ah, al, w1h, w1l, mlp_b1, nullptr, pq1, Mq, HID, Cc, 0, 0, 0);
    split_k<<<(Mq*HID/4 + 255)/256, 256>>>(pq1, ah, al, Mq*HID/4);
    gemm_bf<1, 2, false><<<dim3(HID/128, 10, 1), 256>>>(
        ah, al, w2h, w2l, mlp_b2, nullptr, pq2, Mq, HID, HID, 0, 0, 0);
    split_k<<<(Mq*HID/4 + 255)/256, 256>>>(pq2, ah, al, Mq*HID/4);
    gemm_bf<0, 2, false><<<dim3(Cc/128, 10, 1), 256>>>(
        ah, al, w3h, w3l, mlp_b3, nullptr, pq1, Mq, Cc, HID, 0, 0, 0);   // q3 in pq1
    split_k<<<(Mq*Cc/4 + 255)/256, 256>>>(pq1, ah, al, Mq*Cc/4);
    gemm_bf<0, 2, false><<<dim3(IDim/128, 10, 1), 256>>>(
        ah, al, qph, qpl, qproj_b, nullptr, pq4, Mq, IDim, Cc, 0, 0, 0); // q4
    split_k<<<(Mq*IDim/4 + 255)/256, 256>>>(pq4, ah, al, Mq*IDim/4);
    gemm_bf<0, 0, false><<<dim3(Cc/128, 10, 1), 256>>>(
        ah, al, sph, spl, nullptr, nullptr, pqq, Mq, Cc, IDim, 0, 0, 0); // qq
    split_k<<<(Mq*Cc/4 + 255)/256, 256>>>(pqq, ah, al, Mq*Cc/4);
    off_kernel<<<(Mq + 255)/256, 256>>>(pq4, sproj_b, head_b, poff);

    // ---- mask GEMM: y transpose-split then batched GEMM ----
    splitT_k<false><<<dim3(HW/32, Cc/32, Bb), tBlock>>>(
        py, bth, btl, nullptr, nullptr, nullptr, nullptr, Cc, HW);
    gemm_bf<0, 0, false><<<dim3(HW/128, 3, Bb), 256>>>(
        ah, al, bth, btl, nullptr, nullptr, pm,
        Nq, HW, Cc, (long)Nq*Cc, (long)HW*Cc, (long)Nq*HW);

    // ---- bilinear 2x upsample + per-(b,n) offset ----
    const long tot4 = (long)Bb * Nq * H2 * (W2 / 4);
    upsample_kernel<<<(unsigned)((tot4 + 255)/256), 256>>>(pm, poff, out);
}

// round 6
// speedup vs baseline: 1.1965x; 1.1965x over previous
#include <cuda_runtime.h>
#include <cuda_bf16.h>
#include <math.h>
#include <stdint.h>

// ---------------- problem constants ----------------
#define Bb 4
#define Cc 256
#define Hh 80
#define Ww 80
#define Nq 300
#define IDim 128
#define HID 512
#define H2 160
#define W2 160
#define HW (Hh*Ww)
#define CHW (Cc*HW)

// ---------------- device scratch ----------------
__device__ float g_x[Bb*CHW];      // block0 output
__device__ float g_y[Bb*CHW];      // block1 output (final spatial)
__device__ float g_t[Bb*CHW];      // dw temp (pre-LN)
__device__ float g_mean[Bb*HW];
__device__ float g_inv[Bb*HW];
__device__ float g_q1[Bb*Nq*HID];
__device__ float g_q2[Bb*Nq*HID];
__device__ float g_q4[Bb*Nq*IDim];
__device__ float g_qq[Bb*Nq*Cc];
__device__ float g_off[Bb*Nq];
__device__ float g_m[Bb*Nq*HW];    // mask at 80x80

__device__ __forceinline__ float gelu_f(float x) {
    return 0.5f * x * (1.0f + erff(x * 0.70710678118654752f));
}
__device__ __forceinline__ uint32_t su32(const void* p) {
    return (uint32_t)__cvta_generic_to_shared(p);
}
__device__ __forceinline__ void ldsm4(uint32_t* r, uint32_t addr) {
    asm volatile("ldmatrix.sync.aligned.m8n8.x4.shared.b16 {%0,%1,%2,%3}, [%4];"
        : "=r"(r[0]), "=r"(r[1]), "=r"(r[2]), "=r"(r[3]) : "r"(addr));
}
__device__ __forceinline__ void ldsm2(uint32_t* r, uint32_t addr) {
    asm volatile("ldmatrix.sync.aligned.m8n8.x2.shared.b16 {%0,%1}, [%2];"
        : "=r"(r[0]), "=r"(r[1]) : "r"(addr));
}
__device__ __forceinline__ void mma16816(float* d, const uint32_t* a, const uint32_t* b) {
    asm volatile("mma.sync.aligned.m16n8k16.row.col.f32.bf16.bf16.f32 "
        "{%0,%1,%2,%3}, {%4,%5,%6,%7}, {%8,%9}, {%0,%1,%2,%3};"
        : "+f"(d[0]), "+f"(d[1]), "+f"(d[2]), "+f"(d[3])
        : "r"(a[0]), "r"(a[1]), "r"(a[2]), "r"(a[3]), "r"(b[0]), "r"(b[1]));
}
__device__ __forceinline__ void split_bf16(float x, __nv_bfloat16& hi, __nv_bfloat16& lo) {
    hi = __float2bfloat16(x);
    lo = __float2bfloat16(x - __bfloat162float(hi));
}

// ---------------- depthwise 3x3 conv (SAME) + bias ----------------
__global__ void dw_kernel(const float* __restrict__ x, const float* __restrict__ w,
                          const float* __restrict__ bia, float* __restrict__ out)
{
    int wq = threadIdx.x;
    int hq = blockIdx.y * 4 + threadIdx.y;
    int plane = blockIdx.z;
    int c = plane & (Cc - 1);
    const float* xp = x + (long)plane * HW;
    const float* wp = w + c * 9;
    float w00 = wp[0], w01 = wp[1], w02 = wp[2];
    float w10 = wp[3], w11 = wp[4], w12 = wp[5];
    float w20 = wp[6], w21 = wp[7], w22 = wp[8];
    float acc = bia[c];

    const float* r0 = xp + (hq - 1) * Ww;
    const float* r1 = xp + hq * Ww;
    const float* r2 = xp + (hq + 1) * Ww;
    bool ht = hq > 0, hb = hq < Hh - 1;
    bool wl = wq > 0, wr = wq < Ww - 1;

    if (ht) {
        if (wl) acc += w00 * r0[wq - 1];
        acc += w01 * r0[wq];
        if (wr) acc += w02 * r0[wq + 1];
    }
    {
        if (wl) acc += w10 * r1[wq - 1];
        acc += w11 * r1[wq];
        if (wr) acc += w12 * r1[wq + 1];
    }
    if (hb) {
        if (wl) acc += w20 * r2[wq - 1];
        acc += w21 * r2[wq];
        if (wr) acc += w22 * r2[wq + 1];
    }
    out[(long)plane * HW + hq * Ww + wq] = acc;
}

// ---------------- LN stats per pixel ----------------
__global__ void stats_kernel(const float* __restrict__ t,
                             float* __restrict__ mean, float* __restrict__ inv)
{
    int p = blockIdx.x * blockDim.x + threadIdx.x;
    if (p >= Bb*HW) return;
    int bb = p / HW;
    int pix = p - bb * HW;
    const float* base = t + (long)bb * CHW + pix;
    float s = 0.f, s2 = 0.f;
#pragma unroll 8
    for (int c = 0; c < Cc; c++) {
        float v = base[(long)c * HW];
        s += v; s2 += v * v;
    }
    float m = s * (1.0f / Cc);
    float var = s2 * (1.0f / Cc) - m * m;
    mean[p] = m;
    inv[p] = rsqrtf(var + 1e-6f);
}

// ---------------- tensor-core GEMM (bf16 3-pass split) ----------------
// C[m,n] = act( sum_k A[m,k] * Bop[k,n] + bias ) (+ resid)
// BMODE 0: Bop = B[k,n] (row stride N), per-thread: 1 n-row, 4 k. LN fusable.
// BMODE 1: Bop = B[n,k] (row stride K).
// Tiles: BM=128, BN=64, BK=16. 8 warps (4m x 2n), warp tile 32x32.
// PADK=24 (48B rows: 16B-aligned for ldmatrix, conflict-light).
#define PADK 24

template<int ACT, int BMODE, int BIASM, bool LNF, bool RES>
__global__ void __launch_bounds__(256, 2)
gemm_tc(const float* __restrict__ A, const float* __restrict__ B,
        const float* __restrict__ bias, const float* __restrict__ resid,
        const float* __restrict__ lnMean, const float* __restrict__ lnInv,
        const float* __restrict__ lnW, const float* __restrict__ lnB,
        float* __restrict__ C, int M, int N, int K,
        long sA, long sB, long sC)
{
    int z = blockIdx.z;
    A += z * sA; B += z * sB; C += z * sC;
    const float* R = RES ? (resid + z * sC) : nullptr;

    int m0 = blockIdx.y * 128;
    int n0 = blockIdx.x * 64;

    __shared__ __align__(16) __nv_bfloat16 As[2][2][128 * PADK];
    __shared__ __align__(16) __nv_bfloat16 Bs[2][2][64 * PADK];

    int tid = threadIdx.x;
    int warp = tid >> 5;
    int lane = tid & 31;
    int wm = warp & 3;        // m offset 32*wm
    int wn = warp >> 2;       // n offset 32*wn

    // ---- loader indices ----
    int arow = tid >> 1;                  // 0..127
    int acol = (tid & 1) * 8;             // 0 or 8
    // BMODE1: one n-row, 4 consecutive k
    int b1row = tid >> 2;                 // 0..63 (n)
    int b1col = (tid & 3) * 4;            // 0..12 (k)
    // BMODE0: one n-row, 4 consecutive k (column-strided global reads)
    int b0n = tid >> 2;                   // 0..63 (n)
    int b0kc = (tid & 3) * 4;             // 0,4,8,12 (k)

    float mea = 0.f, iva = 0.f;
    if (LNF) {
        mea = lnMean[(long)z * N + n0 + b0n];
        iva = lnInv [(long)z * N + n0 + b0n];
    }

    float acc[2][4][4];
#pragma unroll
    for (int i = 0; i < 2; i++)
#pragma unroll
        for (int j = 0; j < 4; j++)
#pragma unroll
            for (int q = 0; q < 4; q++) acc[i][j][q] = 0.f;

    const int KT = K >> 4;
    int gm_ld = m0 + arow;
    bool mok = gm_ld < M;
    const float* Aip = A + (long)gm_ld * K + acol;

    float4 pa0, pa1;
    float bv[4];
    // ---- load chunk 0 ----
    {
        pa0 = mok ? *(const float4*)(Aip + 0) : make_float4(0,0,0,0);
        pa1 = mok ? *(const float4*)(Aip + 4) : make_float4(0,0,0,0);
        if (BMODE == 1) {
            float4 pb = *(const float4*)(B + (long)(n0 + b1row) * K + b1col);
            bv[0]=pb.x; bv[1]=pb.y; bv[2]=pb.z; bv[3]=pb.w;
        } else {
            const float* Bp = B + (long)b0kc * N + n0 + b0n;
            bv[0] = Bp[0]; bv[1] = Bp[N]; bv[2] = Bp[2*N]; bv[3] = Bp[3*N];
            if (LNF) {
                float4 lw4 = *(const float4*)&lnW[b0kc];
                float4 lb4 = *(const float4*)&lnB[b0kc];
                bv[0] = (bv[0] - mea) * iva * lw4.x + lb4.x;
                bv[1] = (bv[1] - mea) * iva * lw4.y + lb4.y;
                bv[2] = (bv[2] - mea) * iva * lw4.z + lb4.z;
                bv[3] = (bv[3] - mea) * iva * lw4.w + lb4.w;
            }
        }
    }
    // ---- store chunk 0 into buf 0 ----
    {
        float v[8] = {pa0.x, pa0.y, pa0.z, pa0.w, pa1.x, pa1.y, pa1.z, pa1.w};
        __nv_bfloat162* p0 = (__nv_bfloat162*)&As[0][0][arow * PADK + acol];
        __nv_bfloat162* p1 = (__nv_bfloat162*)&As[0][1][arow * PADK + acol];
#pragma unroll
        for (int j = 0; j < 4; j++) {
            __nv_bfloat16 h0, l0, h1, l1;
            split_bf16(v[2*j], h0, l0);
            split_bf16(v[2*j+1], h1, l1);
            p0[j] = __nv_bfloat162(h0, h1);
            p1[j] = __nv_bfloat162(l0, l1);
        }
        int brow = (BMODE == 1) ? b1row : b0n;
        int bcol = (BMODE == 1) ? b1col : b0kc;
        __nv_bfloat162* q0 = (__nv_bfloat162*)&Bs[0][0][brow * PADK + bcol];
        __nv_bfloat162* q1 = (__nv_bfloat162*)&Bs[0][1][brow * PADK + bcol];
        __nv_bfloat16 h0,l0,h1,l1,h2,l2,h3,l3;
        split_bf16(bv[0],h0,l0); split_bf16(bv[1],h1,l1);
        split_bf16(bv[2],h2,l2); split_bf16(bv[3],h3,l3);
        q0[0] = __nv_bfloat162(h0,h1); q0[1] = __nv_bfloat162(h2,h3);
        q1[0] = __nv_bfloat162(l0,l1); q1[1] = __nv_bfloat162(l2,l3);
    }
    __syncthreads();

    // ldmatrix address indices
    int a_mrow = lane & 15;
    int a_kh = (lane >> 4) * 8;
    int b_nrow = lane & 7;
    int b_kh = ((lane >> 3) & 1) * 8;

    for (int kt = 0; kt < KT; kt++) {
        int buf = kt & 1;
        // ---- prefetch chunk kt+1 ----
        if (kt + 1 < KT) {
            int kb = (kt + 1) << 4;
            pa0 = mok ? *(const float4*)(Aip + kb + 0) : make_float4(0,0,0,0);
            pa1 = mok ? *(const float4*)(Aip + kb + 4) : make_float4(0,0,0,0);
            if (BMODE == 1) {
                float4 pb = *(const float4*)(B + (long)(n0 + b1row) * K + kb + b1col);
                bv[0]=pb.x; bv[1]=pb.y; bv[2]=pb.z; bv[3]=pb.w;
            } else {
                const float* Bp = B + (long)(kb + b0kc) * N + n0 + b0n;
                bv[0] = Bp[0]; bv[1] = Bp[N]; bv[2] = Bp[2*N]; bv[3] = Bp[3*N];
                if (LNF) {
                    float4 lw4 = *(const float4*)&lnW[kb + b0kc];
                    float4 lb4 = *(const float4*)&lnB[kb + b0kc];
                    bv[0] = (bv[0] - mea) * iva * lw4.x + lb4.x;
                    bv[1] = (bv[1] - mea) * iva * lw4.y + lb4.y;
                    bv[2] = (bv[2] - mea) * iva * lw4.z + lb4.z;
                    bv[3] = (bv[3] - mea) * iva * lw4.w + lb4.w;
                }
            }
        }

        // ---- compute on buf ----
        uint32_t afr[2][2][4];
        uint32_t bfr[2][4][2];
#pragma unroll
        for (int s = 0; s < 2; s++) {
#pragma unroll
            for (int mt = 0; mt < 2; mt++) {
                uint32_t addr = su32(&As[buf][s][(wm*32 + mt*16 + a_mrow) * PADK + a_kh]);
                ldsm4(afr[s][mt], addr);
            }
#pragma unroll
            for (int nt = 0; nt < 4; nt++) {
                uint32_t addr = su32(&Bs[buf][s][(wn*32 + nt*8 + b_nrow) * PADK + b_kh]);
                ldsm2(bfr[s][nt], addr);
            }
        }
#pragma unroll
        for (int mt = 0; mt < 2; mt++)
#pragma unroll
            for (int nt = 0; nt < 4; nt++) {
                mma16816(acc[mt][nt], afr[0][mt], bfr[0][nt]);  // hi*hi
                mma16816(acc[mt][nt], afr[0][mt], bfr[1][nt]);  // hi*lo
                mma16816(acc[mt][nt], afr[1][mt], bfr[0][nt]);  // lo*hi
            }

        // ---- store prefetched chunk ----
        if (kt + 1 < KT) {
            int nb = buf ^ 1;
            float v[8] = {pa0.x, pa0.y, pa0.z, pa0.w, pa1.x, pa1.y, pa1.z, pa1.w};
            __nv_bfloat162* p0 = (__nv_bfloat162*)&As[nb][0][arow * PADK + acol];
            __nv_bfloat162* p1 = (__nv_bfloat162*)&As[nb][1][arow * PADK + acol];
#pragma unroll
            for (int j = 0; j < 4; j++) {
                __nv_bfloat16 h0, l0, h1, l1;
                split_bf16(v[2*j], h0, l0);
                split_bf16(v[2*j+1], h1, l1);
                p0[j] = __nv_bfloat162(h0, h1);
                p1[j] = __nv_bfloat162(l0, l1);
            }
            int brow = (BMODE == 1) ? b1row : b0n;
            int bcol = (BMODE == 1) ? b1col : b0kc;
            __nv_bfloat162* q0 = (__nv_bfloat162*)&Bs[nb][0][brow * PADK + bcol];
            __nv_bfloat162* q1 = (__nv_bfloat162*)&Bs[nb][1][brow * PADK + bcol];
            __nv_bfloat16 h0,l0,h1,l1,h2,l2,h3,l3;
            split_bf16(bv[0],h0,l0); split_bf16(bv[1],h1,l1);
            split_bf16(bv[2],h2,l2); split_bf16(bv[3],h3,l3);
            q0[0] = __nv_bfloat162(h0,h1); q0[1] = __nv_bfloat162(h2,h3);
            q1[0] = __nv_bfloat162(l0,l1); q1[1] = __nv_bfloat162(l2,l3);
            __syncthreads();
        }
    }

    // ---- epilogue ----
#pragma unroll
    for (int mt = 0; mt < 2; mt++) {
#pragma unroll
        for (int nt = 0; nt < 4; nt++) {
            int gn = n0 + wn*32 + nt*8 + (lane & 3) * 2;
            float bn0v = 0.f, bn1v = 0.f;
            if (BIASM == 2) { bn0v = bias[gn]; bn1v = bias[gn + 1]; }
#pragma unroll
            for (int h = 0; h < 2; h++) {
                int row = m0 + wm*32 + mt*16 + (lane >> 2) + h*8;
                if (row >= M) continue;
                float x0 = acc[mt][nt][h*2 + 0];
                float x1 = acc[mt][nt][h*2 + 1];
                if (BIASM == 1) { float bm = bias[row]; x0 += bm; x1 += bm; }
                if (BIASM == 2) { x0 += bn0v; x1 += bn1v; }
                if (ACT == 1) { x0 = fmaxf(x0, 0.f); x1 = fmaxf(x1, 0.f); }
                if (ACT == 2) { x0 = gelu_f(x0); x1 = gelu_f(x1); }
                if (RES) {
                    float2 r2 = *(const float2*)&R[(long)row * N + gn];
                    x0 += r2.x; x1 += r2.y;
                }
                float2 o; o.x = x0; o.y = x1;
                *(float2*)&C[(long)row * N + gn] = o;
            }
        }
    }
}

// ---------------- per-query offset ----------------
__global__ void off_kernel(const float* __restrict__ q4, const float* __restrict__ sb,
                           const float* __restrict__ hb, float* __restrict__ off)
{
    int n = blockIdx.x * blockDim.x + threadIdx.x;
    if (n >= Bb*Nq) return;
    float s = hb[0];
#pragma unroll 8
    for (int i = 0; i < IDim; i++) s += q4[(long)n * IDim + i] * sb[i];
    off[n] = s;
}

// ---------------- bilinear 2x upsample + offset ----------------
__global__ void upsample_kernel(const float* __restrict__ m, const float* __restrict__ off,
                                float* __restrict__ out)
{
    long idx = (long)blockIdx.x * blockDim.x + threadIdx.x;
    const long tot4 = (long)Bb * Nq * H2 * (W2 / 4);
    if (idx >= tot4) return;
    int wq4 = (int)(idx % (W2 / 4)) * 4;
    int h2 = (int)((idx / (W2 / 4)) % H2);
    long bn = idx / ((long)(W2 / 4) * H2);

    float fh = h2 * 0.5f - 0.25f;
    int h0f = (int)floorf(fh);
    float wh = fh - (float)h0f;
    int h0 = max(h0f, 0), h1 = min(h0f + 1, Hh - 1);

    const float* r0 = m + bn * (long)HW + h0 * Ww;
    const float* r1 = m + bn * (long)HW + h1 * Ww;
    float o = off[bn];

    float r[4];
#pragma unroll
    for (int j = 0; j < 4; j++) {
        int w2 = wq4 + j;
        float fw = w2 * 0.5f - 0.25f;
        int w0f = (int)floorf(fw);
        float ww = fw - (float)w0f;
        int w0 = max(w0f, 0), w1 = min(w0f + 1, Ww - 1);
        float t0 = r0[w0] * (1.f - ww) + r0[w1] * ww;
        float t1 = r1[w0] * (1.f - ww) + r1[w1] * ww;
        r[j] = t0 * (1.f - wh) + t1 * wh + o;
    }
    float4 v = make_float4(r[0], r[1], r[2], r[3]);
    *(float4*)(out + bn * (long)(H2 * W2) + (long)h2 * W2 + wq4) = v;
}

// ---------------- launcher ----------------
extern "C" void kernel_launch(void* const* d_in, const int* in_sizes, int n_in,
                              void* d_out, int out_size)
{
    const float* spat    = (const float*)d_in[0];
    const float* qf      = (const float*)d_in[1];
    const float* dw_w    = (const float*)d_in[2];
    const float* dw_b    = (const float*)d_in[3];
    const float* ln_w    = (const float*)d_in[4];
    const float* ln_b    = (const float*)d_in[5];
    const float* pw_w    = (const float*)d_in[6];
    const float* pw_b    = (const float*)d_in[7];
    const float* sproj_w = (const float*)d_in[8];
    const float* sproj_b = (const float*)d_in[9];
    const float* mlp_w1  = (const float*)d_in[10];
    const float* mlp_b1  = (const float*)d_in[11];
    const float* mlp_w2  = (const float*)d_in[12];
    const float* mlp_b2  = (const float*)d_in[13];
    const float* mlp_w3  = (const float*)d_in[14];
    const float* mlp_b3  = (const float*)d_in[15];
    const float* qproj_w = (const float*)d_in[16];
    const float* qproj_b = (const float*)d_in[17];
    const float* head_b  = (const float*)d_in[18];
    float* out = (float*)d_out;

    float *px, *py, *pt, *pmean, *pinv, *pq1, *pq2, *pq4, *pqq, *poff, *pm;
    cudaGetSymbolAddress((void**)&px,    g_x);
    cudaGetSymbolAddress((void**)&py,    g_y);
    cudaGetSymbolAddress((void**)&pt,    g_t);
    cudaGetSymbolAddress((void**)&pmean, g_mean);
    cudaGetSymbolAddress((void**)&pinv,  g_inv);
    cudaGetSymbolAddress((void**)&pq1,   g_q1);
    cudaGetSymbolAddress((void**)&pq2,   g_q2);
    cudaGetSymbolAddress((void**)&pq4,   g_q4);
    cudaGetSymbolAddress((void**)&pqq,   g_qq);
    cudaGetSymbolAddress((void**)&poff,  g_off);
    cudaGetSymbolAddress((void**)&pm,    g_m);

    dim3 dwBlock(80, 4);
    dim3 dwGrid(1, Hh / 4, Bb * Cc);
    const int pix = Bb * HW;
    const int Mq = Bb * Nq;

    // Launch #1..#3: dw0, stats0, mlp1 (mlp1 independent of spatial path)
    dw_kernel<<<dwGrid, dwBlock>>>(spat, dw_w, dw_b, pt);
    stats_kernel<<<(pix + 255)/256, 256>>>(pt, pmean, pinv);
    gemm_tc<1, 1, 2, false, false><<<dim3(HID / 64, (Mq + 127) / 128, 1), 256>>>(
        qf, mlp_w1, mlp_b1, nullptr, nullptr, nullptr, nullptr, nullptr,
        pq1, Mq, HID, Cc, 0, 0, 0);

    // Launch #4: pw GEMM block0 (profiling target)
    gemm_tc<2, 0, 1, true, true><<<dim3(HW / 64, 2, Bb), 256>>>(
        pw_w, pt, pw_b, spat, pmean, pinv, ln_w, ln_b,
        px, Cc, HW, Cc, 0, CHW, CHW);

    // ---- spatial block 1 ----
    dw_kernel<<<dwGrid, dwBlock>>>(px, dw_w + Cc * 9, dw_b + Cc, pt);
    stats_kernel<<<(pix + 255)/256, 256>>>(pt, pmean, pinv);
    gemm_tc<2, 0, 1, true, true><<<dim3(HW / 64, 2, Bb), 256>>>(
        pw_w + Cc * Cc, pt, pw_b + Cc, px, pmean, pinv, ln_w + Cc, ln_b + Cc,
        py, Cc, HW, Cc, 0, CHW, CHW);

    // ---- rest of query MLP chain ----
    gemm_tc<1, 1, 2, false, false><<<dim3(HID / 64, (Mq + 127) / 128, 1), 256>>>(
        pq1, mlp_w2, mlp_b2, nullptr, nullptr, nullptr, nullptr, nullptr,
        pq2, Mq, HID, HID, 0, 0, 0);
    gemm_tc<0, 1, 2, false, false><<<dim3(Cc / 64, (Mq + 127) / 128, 1), 256>>>(
        pq2, mlp_w3, mlp_b3, nullptr, nullptr, nullptr, nullptr, nullptr,
        pq1, Mq, Cc, HID, 0, 0, 0);                 // q3 (reuse q1)
    gemm_tc<0, 1, 2, false, false><<<dim3(IDim / 64, (Mq + 127) / 128, 1), 256>>>(
        pq1, qproj_w, qproj_b, nullptr, nullptr, nullptr, nullptr, nullptr,
        pq4, Mq, IDim, Cc, 0, 0, 0);                // q4
    // fold sproj into query side: qq[n,c] = sum_id q4[n,id] * sproj_w[id,c]
    gemm_tc<0, 0, 0, false, false><<<dim3(Cc / 64, (Mq + 127) / 128, 1), 256>>>(
        pq4, sproj_w, nullptr, nullptr, nullptr, nullptr, nullptr, nullptr,
        pqq, Mq, Cc, IDim, 0, 0, 0);
    off_kernel<<<(Mq + 255)/256, 256>>>(pq4, sproj_b, head_b, poff);

    // ---- mask GEMM at 80x80 ----
    gemm_tc<0, 0, 0, false, false><<<dim3(HW / 64, (Nq + 127) / 128, Bb), 256>>>(
        pqq, py, nullptr, nullptr, nullptr, nullptr, nullptr, nullptr,
        pm, Nq, HW, Cc, (long)Nq * Cc, (long)CHW, (long)Nq * HW);

    // ---- bilinear 2x upsample + per-(b,n) offset ----
    const long tot4 = (long)Bb * Nq * H2 * (W2 / 4);
    upsample_kernel<<<(unsigned)((tot4 + 255)/256), 256>>>(pm, poff, out);
}

// round 7
// speedup vs baseline: 1.2029x; 1.0054x over previous
#include <cuda_runtime.h>
#include <cuda_bf16.h>
#include <math.h>
#include <stdint.h>
#include <string.h>

// ---------------- problem constants ----------------
#define Bb 4
#define Cc 256
#define Hh 80
#define Ww 80
#define Nq 300
#define IDim 128
#define HID 512
#define H2 160
#define W2 160
#define HW (Hh*Ww)
#define CHW (Cc*HW)

// ---------------- device scratch ----------------
__device__ float g_x[Bb*CHW];
__device__ float g_y[Bb*CHW];
__device__ float g_t[Bb*CHW];
__device__ float g_mean[Bb*HW];
__device__ float g_inv[Bb*HW];
__device__ float g_q1[Bb*Nq*HID];
__device__ float g_q2[Bb*Nq*HID];
__device__ float g_q4[Bb*Nq*IDim];
__device__ float g_qq[Bb*Nq*Cc];
__device__ float g_off[Bb*Nq];
__device__ float g_m[Bb*Nq*HW];

__device__ __forceinline__ float gelu_f(float x) {
    return 0.5f * x * (1.0f + erff(x * 0.70710678118654752f));
}
__device__ __forceinline__ uint32_t su32(const void* p) {
    return (uint32_t)__cvta_generic_to_shared(p);
}
__device__ __forceinline__ void ldsm4(uint32_t* r, uint32_t addr) {
    asm volatile("ldmatrix.sync.aligned.m8n8.x4.shared.b16 {%0,%1,%2,%3}, [%4];"
        : "=r"(r[0]), "=r"(r[1]), "=r"(r[2]), "=r"(r[3]) : "r"(addr));
}
__device__ __forceinline__ void mma16816(float* d, const uint32_t* a, const uint32_t* b) {
    asm volatile("mma.sync.aligned.m16n8k16.row.col.f32.bf16.bf16.f32 "
        "{%0,%1,%2,%3}, {%4,%5,%6,%7}, {%8,%9}, {%0,%1,%2,%3};"
        : "+f"(d[0]), "+f"(d[1]), "+f"(d[2]), "+f"(d[3])
        : "r"(a[0]), "r"(a[1]), "r"(a[2]), "r"(a[3]), "r"(b[0]), "r"(b[1]));
}
__device__ __forceinline__ void split_bf16(float x, __nv_bfloat16& hi, __nv_bfloat16& lo) {
    hi = __float2bfloat16(x);
    lo = __float2bfloat16(x - __bfloat162float(hi));
}
__device__ __forceinline__ uint32_t pk2(__nv_bfloat16 a, __nv_bfloat16 b) {
    __nv_bfloat162 t(a, b);
    uint32_t u;
    memcpy(&u, &t, 4);
    return u;
}

// ---------------- depthwise 3x3 conv (SAME) + bias ----------------
__global__ void dw_kernel(const float* __restrict__ x, const float* __restrict__ w,
                          const float* __restrict__ bia, float* __restrict__ out)
{
    int wq = threadIdx.x;
    int hq = blockIdx.y * 4 + threadIdx.y;
    int plane = blockIdx.z;
    int c = plane & (Cc - 1);
    const float* xp = x + (long)plane * HW;
    const float* wp = w + c * 9;
    float w00 = wp[0], w01 = wp[1], w02 = wp[2];
    float w10 = wp[3], w11 = wp[4], w12 = wp[5];
    float w20 = wp[6], w21 = wp[7], w22 = wp[8];
    float acc = bia[c];

    const float* r0 = xp + (hq - 1) * Ww;
    const float* r1 = xp + hq * Ww;
    const float* r2 = xp + (hq + 1) * Ww;
    bool ht = hq > 0, hb = hq < Hh - 1;
    bool wl = wq > 0, wr = wq < Ww - 1;

    if (ht) {
        if (wl) acc += w00 * r0[wq - 1];
        acc += w01 * r0[wq];
        if (wr) acc += w02 * r0[wq + 1];
    }
    {
        if (wl) acc += w10 * r1[wq - 1];
        acc += w11 * r1[wq];
        if (wr) acc += w12 * r1[wq + 1];
    }
    if (hb) {
        if (wl) acc += w20 * r2[wq - 1];
        acc += w21 * r2[wq];
        if (wr) acc += w22 * r2[wq + 1];
    }
    out[(long)plane * HW + hq * Ww + wq] = acc;
}

// ---------------- LN stats per pixel ----------------
__global__ void stats_kernel(const float* __restrict__ t,
                             float* __restrict__ mean, float* __restrict__ inv)
{
    int p = blockIdx.x * blockDim.x + threadIdx.x;
    if (p >= Bb*HW) return;
    int bb = p / HW;
    int pix = p - bb * HW;
    const float* base = t + (long)bb * CHW + pix;
    float s = 0.f, s2 = 0.f;
#pragma unroll 8
    for (int c = 0; c < Cc; c++) {
        float v = base[(long)c * HW];
        s += v; s2 += v * v;
    }
    float m = s * (1.0f / Cc);
    float var = s2 * (1.0f / Cc) - m * m;
    mean[p] = m;
    inv[p] = rsqrtf(var + 1e-6f);
}

// ---------------- tensor-core GEMM (bf16 3-pass split) ----------------
// BM=128, BN=64, BK=16. 8 warps (4m x 2n), warp tile 32x32.
// Packed STS (uint4 A-plane, uint2 B-plane), all fragment loads via ldsm4.
#define PADK 24

template<int ACT, int BMODE, int BIASM, bool LNF, bool RES>
__global__ void __launch_bounds__(256, 2)
gemm_tc(const float* __restrict__ A, const float* __restrict__ B,
        const float* __restrict__ bias, const float* __restrict__ resid,
        const float* __restrict__ lnMean, const float* __restrict__ lnInv,
        const float* __restrict__ lnW, const float* __restrict__ lnB,
        float* __restrict__ C, int M, int N, int K,
        long sA, long sB, long sC)
{
    int z = blockIdx.z;
    A += z * sA; B += z * sB; C += z * sC;
    const float* R = RES ? (resid + z * sC) : nullptr;

    int m0 = blockIdx.y * 128;
    int n0 = blockIdx.x * 64;

    __shared__ __align__(16) __nv_bfloat16 As[2][2][128 * PADK];
    __shared__ __align__(16) __nv_bfloat16 Bs[2][2][64 * PADK];

    int tid = threadIdx.x;
    int warp = tid >> 5;
    int lane = tid & 31;
    int wm = warp & 3;
    int wn = warp >> 2;

    // loader indices
    int arow = tid >> 1;
    int acol = (tid & 1) * 8;
    int b1row = tid >> 2;
    int b1col = (tid & 3) * 4;
    int b0n = tid >> 2;
    int b0kc = (tid & 3) * 4;

    float mea = 0.f, iva = 0.f;
    if (LNF) {
        mea = lnMean[(long)z * N + n0 + b0n];
        iva = lnInv [(long)z * N + n0 + b0n];
    }

    float acc[2][4][4];
#pragma unroll
    for (int i = 0; i < 2; i++)
#pragma unroll
        for (int j = 0; j < 4; j++)
#pragma unroll
            for (int q = 0; q < 4; q++) acc[i][j][q] = 0.f;

    const int KT = K >> 4;
    int gm_ld = m0 + arow;
    bool mok = gm_ld < M;
    const float* Aip = A + (long)gm_ld * K + acol;

    int brow = (BMODE == 1) ? b1row : b0n;
    int bcol = (BMODE == 1) ? b1col : b0kc;

    float4 pa0, pa1;
    float bv[4];

    // ---- load chunk 0 ----
    {
        pa0 = mok ? *(const float4*)(Aip + 0) : make_float4(0,0,0,0);
        pa1 = mok ? *(const float4*)(Aip + 4) : make_float4(0,0,0,0);
        if (BMODE == 1) {
            float4 pb = *(const float4*)(B + (long)(n0 + b1row) * K + b1col);
            bv[0]=pb.x; bv[1]=pb.y; bv[2]=pb.z; bv[3]=pb.w;
        } else {
            const float* Bp = B + (long)b0kc * N + n0 + b0n;
            bv[0] = Bp[0]; bv[1] = Bp[N]; bv[2] = Bp[2*N]; bv[3] = Bp[3*N];
            if (LNF) {
                float4 lw4 = *(const float4*)&lnW[b0kc];
                float4 lb4 = *(const float4*)&lnB[b0kc];
                bv[0] = (bv[0] - mea) * iva * lw4.x + lb4.x;
                bv[1] = (bv[1] - mea) * iva * lw4.y + lb4.y;
                bv[2] = (bv[2] - mea) * iva * lw4.z + lb4.z;
                bv[3] = (bv[3] - mea) * iva * lw4.w + lb4.w;
            }
        }
    }
    // ---- store chunk 0 (packed) ----
    {
        float v[8] = {pa0.x, pa0.y, pa0.z, pa0.w, pa1.x, pa1.y, pa1.z, pa1.w};
        __nv_bfloat16 h[8], l[8];
#pragma unroll
        for (int j = 0; j < 8; j++) split_bf16(v[j], h[j], l[j]);
        uint4 uh = make_uint4(pk2(h[0],h[1]), pk2(h[2],h[3]), pk2(h[4],h[5]), pk2(h[6],h[7]));
        uint4 ul = make_uint4(pk2(l[0],l[1]), pk2(l[2],l[3]), pk2(l[4],l[5]), pk2(l[6],l[7]));
        *(uint4*)&As[0][0][arow * PADK + acol] = uh;
        *(uint4*)&As[0][1][arow * PADK + acol] = ul;
        __nv_bfloat16 bh[4], bl[4];
#pragma unroll
        for (int j = 0; j < 4; j++) split_bf16(bv[j], bh[j], bl[j]);
        *(uint2*)&Bs[0][0][brow * PADK + bcol] = make_uint2(pk2(bh[0],bh[1]), pk2(bh[2],bh[3]));
        *(uint2*)&Bs[0][1][brow * PADK + bcol] = make_uint2(pk2(bl[0],bl[1]), pk2(bl[2],bl[3]));
    }
    __syncthreads();

    // ldmatrix per-lane indices
    int a_mrow = lane & 15;
    int a_kh = (lane >> 4) * 8;
    // B x4: grp = lane>>3; row += ((grp>>1)&1)*8, col = (grp&1)*8
    int b_row = ((lane >> 4) & 1) * 8 + (lane & 7);
    int b_kh = ((lane >> 3) & 1) * 8;

    for (int kt = 0; kt < KT; kt++) {
        int buf = kt & 1;
        // ---- prefetch chunk kt+1 ----
        if (kt + 1 < KT) {
            int kb = (kt + 1) << 4;
            pa0 = mok ? *(const float4*)(Aip + kb + 0) : make_float4(0,0,0,0);
            pa1 = mok ? *(const float4*)(Aip + kb + 4) : make_float4(0,0,0,0);
            if (BMODE == 1) {
                float4 pb = *(const float4*)(B + (long)(n0 + b1row) * K + kb + b1col);
                bv[0]=pb.x; bv[1]=pb.y; bv[2]=pb.z; bv[3]=pb.w;
            } else {
                const float* Bp = B + (long)(kb + b0kc) * N + n0 + b0n;
                bv[0] = Bp[0]; bv[1] = Bp[N]; bv[2] = Bp[2*N]; bv[3] = Bp[3*N];
                if (LNF) {
                    float4 lw4 = *(const float4*)&lnW[kb + b0kc];
                    float4 lb4 = *(const float4*)&lnB[kb + b0kc];
                    bv[0] = (bv[0] - mea) * iva * lw4.x + lb4.x;
                    bv[1] = (bv[1] - mea) * iva * lw4.y + lb4.y;
                    bv[2] = (bv[2] - mea) * iva * lw4.z + lb4.z;
                    bv[3] = (bv[3] - mea) * iva * lw4.w + lb4.w;
                }
            }
        }

        // ---- compute on buf ----
        uint32_t afr[2][2][4];
        uint32_t bfr[2][4];     // [split][4 regs]: covers both nt pairs per x4
#pragma unroll
        for (int s = 0; s < 2; s++) {
#pragma unroll
            for (int mt = 0; mt < 2; mt++) {
                uint32_t addr = su32(&As[buf][s][(wm*32 + mt*16 + a_mrow) * PADK + a_kh]);
                ldsm4(afr[s][mt], addr);
            }
        }
#pragma unroll
        for (int p = 0; p < 2; p++) {
            // one ldsm4 per split covers n rows [wn*32+p*16, +16) x k16
            uint32_t bb0[4], bb1[4];
            uint32_t addr0 = su32(&Bs[buf][0][(wn*32 + p*16 + b_row) * PADK + b_kh]);
            uint32_t addr1 = su32(&Bs[buf][1][(wn*32 + p*16 + b_row) * PADK + b_kh]);
            ldsm4(bb0, addr0);
            ldsm4(bb1, addr1);
#pragma unroll
            for (int mt = 0; mt < 2; mt++) {
                // nt = 2p: regs {bb[0], bb[1]}; nt = 2p+1: {bb[2], bb[3]}
                mma16816(acc[mt][2*p],   afr[0][mt], bb0);       // hi*hi
                mma16816(acc[mt][2*p],   afr[0][mt], bb1);       // hi*lo
                mma16816(acc[mt][2*p],   afr[1][mt], bb0);       // lo*hi
                mma16816(acc[mt][2*p+1], afr[0][mt], bb0 + 2);
                mma16816(acc[mt][2*p+1], afr[0][mt], bb1 + 2);
                mma16816(acc[mt][2*p+1], afr[1][mt], bb0 + 2);
            }
        }

        // ---- store prefetched chunk (packed) ----
        if (kt + 1 < KT) {
            int nb = buf ^ 1;
            float v[8] = {pa0.x, pa0.y, pa0.z, pa0.w, pa1.x, pa1.y, pa1.z, pa1.w};
            __nv_bfloat16 h[8], l[8];
#pragma unroll
            for (int j = 0; j < 8; j++) split_bf16(v[j], h[j], l[j]);
            uint4 uh = make_uint4(pk2(h[0],h[1]), pk2(h[2],h[3]), pk2(h[4],h[5]), pk2(h[6],h[7]));
            uint4 ul = make_uint4(pk2(l[0],l[1]), pk2(l[2],l[3]), pk2(l[4],l[5]), pk2(l[6],l[7]));
            *(uint4*)&As[nb][0][arow * PADK + acol] = uh;
            *(uint4*)&As[nb][1][arow * PADK + acol] = ul;
            __nv_bfloat16 bh[4], bl[4];
#pragma unroll
            for (int j = 0; j < 4; j++) split_bf16(bv[j], bh[j], bl[j]);
            *(uint2*)&Bs[nb][0][brow * PADK + bcol] = make_uint2(pk2(bh[0],bh[1]), pk2(bh[2],bh[3]));
            *(uint2*)&Bs[nb][1][brow * PADK + bcol] = make_uint2(pk2(bl[0],bl[1]), pk2(bl[2],bl[3]));
            __syncthreads();
        }
    }

    // ---- epilogue ----
#pragma unroll
    for (int mt = 0; mt < 2; mt++) {
#pragma unroll
        for (int nt = 0; nt < 4; nt++) {
            int gn = n0 + wn*32 + nt*8 + (lane & 3) * 2;
            float bn0v = 0.f, bn1v = 0.f;
            if (BIASM == 2) { bn0v = bias[gn]; bn1v = bias[gn + 1]; }
#pragma unroll
            for (int h = 0; h < 2; h++) {
                int row = m0 + wm*32 + mt*16 + (lane >> 2) + h*8;
                if (row >= M) continue;
                float x0 = acc[mt][nt][h*2 + 0];
                float x1 = acc[mt][nt][h*2 + 1];
                if (BIASM == 1) { float bm = bias[row]; x0 += bm; x1 += bm; }
                if (BIASM == 2) { x0 += bn0v; x1 += bn1v; }
                if (ACT == 1) { x0 = fmaxf(x0, 0.f); x1 = fmaxf(x1, 0.f); }
                if (ACT == 2) { x0 = gelu_f(x0); x1 = gelu_f(x1); }
                if (RES) {
                    float2 r2 = *(const float2*)&R[(long)row * N + gn];
                    x0 += r2.x; x1 += r2.y;
                }
                float2 o; o.x = x0; o.y = x1;
                *(float2*)&C[(long)row * N + gn] = o;
            }
        }
    }
}

// ---------------- per-query offset ----------------
__global__ void off_kernel(const float* __restrict__ q4, const float* __restrict__ sb,
                           const float* __restrict__ hb, float* __restrict__ off)
{
    int n = blockIdx.x * blockDim.x + threadIdx.x;
    if (n >= Bb*Nq) return;
    float s = hb[0];
#pragma unroll 8
    for (int i = 0; i < IDim; i++) s += q4[(long)n * IDim + i] * sb[i];
    off[n] = s;
}

// ---------------- bilinear 2x upsample + offset ----------------
__global__ void upsample_kernel(const float* __restrict__ m, const float* __restrict__ off,
                                float* __restrict__ out)
{
    long idx = (long)blockIdx.x * blockDim.x + threadIdx.x;
    const long tot4 = (long)Bb * Nq * H2 * (W2 / 4);
    if (idx >= tot4) return;
    int wq4 = (int)(idx % (W2 / 4)) * 4;
    int h2 = (int)((idx / (W2 / 4)) % H2);
    long bn = idx / ((long)(W2 / 4) * H2);

    float fh = h2 * 0.5f - 0.25f;
    int h0f = (int)floorf(fh);
    float wh = fh - (float)h0f;
    int h0 = max(h0f, 0), h1 = min(h0f + 1, Hh - 1);

    const float* r0 = m + bn * (long)HW + h0 * Ww;
    const float* r1 = m + bn * (long)HW + h1 * Ww;
    float o = off[bn];

    float r[4];
#pragma unroll
    for (int j = 0; j < 4; j++) {
        int w2 = wq4 + j;
        float fw = w2 * 0.5f - 0.25f;
        int w0f = (int)floorf(fw);
        float ww = fw - (float)w0f;
        int w0 = max(w0f, 0), w1 = min(w0f + 1, Ww - 1);
        float t0 = r0[w0] * (1.f - ww) + r0[w1] * ww;
        float t1 = r1[w0] * (1.f - ww) + r1[w1] * ww;
        r[j] = t0 * (1.f - wh) + t1 * wh + o;
    }
    float4 v = make_float4(r[0], r[1], r[2], r[3]);
    *(float4*)(out + bn * (long)(H2 * W2) + (long)h2 * W2 + wq4) = v;
}

// ---------------- launcher ----------------
extern "C" void kernel_launch(void* const* d_in, const int* in_sizes, int n_in,
                              void* d_out, int out_size)
{
    const float* spat    = (const float*)d_in[0];
    const float* qf      = (const float*)d_in[1];
    const float* dw_w    = (const float*)d_in[2];
    const float* dw_b    = (const float*)d_in[3];
    const float* ln_w    = (const float*)d_in[4];
    const float* ln_b    = (const float*)d_in[5];
    const float* pw_w    = (const float*)d_in[6];
    const float* pw_b    = (const float*)d_in[7];
    const float* sproj_w = (const float*)d_in[8];
    const float* sproj_b = (const float*)d_in[9];
    const float* mlp_w1  = (const float*)d_in[10];
    const float* mlp_b1  = (const float*)d_in[11];
    const float* mlp_w2  = (const float*)d_in[12];
    const float* mlp_b2  = (const float*)d_in[13];
    const float* mlp_w3  = (const float*)d_in[14];
    const float* mlp_b3  = (const float*)d_in[15];
    const float* qproj_w = (const float*)d_in[16];
    const float* qproj_b = (const float*)d_in[17];
    const float* head_b  = (const float*)d_in[18];
    float* out = (float*)d_out;

    float *px, *py, *pt, *pmean, *pinv, *pq1, *pq2, *pq4, *pqq, *poff, *pm;
    cudaGetSymbolAddress((void**)&px,    g_x);
    cudaGetSymbolAddress((void**)&py,    g_y);
    cudaGetSymbolAddress((void**)&pt,    g_t);
    cudaGetSymbolAddress((void**)&pmean, g_mean);
    cudaGetSymbolAddress((void**)&pinv,  g_inv);
    cudaGetSymbolAddress((void**)&pq1,   g_q1);
    cudaGetSymbolAddress((void**)&pq2,   g_q2);
    cudaGetSymbolAddress((void**)&pq4,   g_q4);
    cudaGetSymbolAddress((void**)&pqq,   g_qq);
    cudaGetSymbolAddress((void**)&poff,  g_off);
    cudaGetSymbolAddress((void**)&pm,    g_m);

    dim3 dwBlock(80, 4);
    dim3 dwGrid(1, Hh / 4, Bb * Cc);
    const int pix = Bb * HW;
    const int Mq = Bb * Nq;

    // Launch #1..#3: dw0, stats0, mlp1 (independent)
    dw_kernel<<<dwGrid, dwBlock>>>(spat, dw_w, dw_b, pt);
    stats_kernel<<<(pix + 255)/256, 256>>>(pt, pmean, pinv);
    gemm_tc<1, 1, 2, false, false><<<dim3(HID / 64, (Mq + 127) / 128, 1), 256>>>(
        qf, mlp_w1, mlp_b1, nullptr, nullptr, nullptr, nullptr, nullptr,
        pq1, Mq, HID, Cc, 0, 0, 0);

    // Launch #4: pw GEMM block0 (profiling target)
    gemm_tc<2, 0, 1, true, true><<<dim3(HW / 64, 2, Bb), 256>>>(
        pw_w, pt, pw_b, spat, pmean, pinv, ln_w, ln_b,
        px, Cc, HW, Cc, 0, CHW, CHW);

    // ---- spatial block 1 ----
    dw_kernel<<<dwGrid, dwBlock>>>(px, dw_w + Cc * 9, dw_b + Cc, pt);
    stats_kernel<<<(pix + 255)/256, 256>>>(pt, pmean, pinv);
    gemm_tc<2, 0, 1, true, true><<<dim3(HW / 64, 2, Bb), 256>>>(
        pw_w + Cc * Cc, pt, pw_b + Cc, px, pmean, pinv, ln_w + Cc, ln_b + Cc,
        py, Cc, HW, Cc, 0, CHW, CHW);

    // ---- rest of query MLP chain ----
    gemm_tc<1, 1, 2, false, false><<<dim3(HID / 64, (Mq + 127) / 128, 1), 256>>>(
        pq1, mlp_w2, mlp_b2, nullptr, nullptr, nullptr, nullptr, nullptr,
        pq2, Mq, HID, HID, 0, 0, 0);
    gemm_tc<0, 1, 2, false, false><<<dim3(Cc / 64, (Mq + 127) / 128, 1), 256>>>(
        pq2, mlp_w3, mlp_b3, nullptr, nullptr, nullptr, nullptr, nullptr,
        pq1, Mq, Cc, HID, 0, 0, 0);
    gemm_tc<0, 1, 2, false, false><<<dim3(IDim / 64, (Mq + 127) / 128, 1), 256>>>(
        pq1, qproj_w, qproj_b, nullptr, nullptr, nullptr, nullptr, nullptr,
        pq4, Mq, IDim, Cc, 0, 0, 0);
    gemm_tc<0, 0, 0, false, false><<<dim3(Cc / 64, (Mq + 127) / 128, 1), 256>>>(
        pq4, sproj_w, nullptr, nullptr, nullptr, nullptr, nullptr, nullptr,
        pqq, Mq, Cc, IDim, 0, 0, 0);
    off_kernel<<<(Mq + 255)/256, 256>>>(pq4, sproj_b, head_b, poff);

    // ---- mask GEMM at 80x80 ----
    gemm_tc<0, 0, 0, false, false><<<dim3(HW / 64, (Nq + 127) / 128, Bb), 256>>>(
        pqq, py, nullptr, nullptr, nullptr, nullptr, nullptr, nullptr,
        pm, Nq, HW, Cc, (long)Nq * Cc, (long)CHW, (long)Nq * HW);

    // ---- bilinear 2x upsample + per-(b,n) offset ----
    const long tot4 = (long)Bb * Nq * H2 * (W2 / 4);
    upsample_kernel<<<(unsigned)((tot4 + 255)/256), 256>>>(pm, poff, out);
}

// round 8
// speedup vs baseline: 1.2627x; 1.0497x over previous
#include <cuda_runtime.h>
#include <cuda_bf16.h>
#include <math.h>
#include <stdint.h>
#include <string.h>

// ---------------- problem constants ----------------
#define Bb 4
#define Cc 256
#define Hh 80
#define Ww 80
#define Nq 300
#define IDim 128
#define HID 512
#define H2 160
#define W2 160
#define HW (Hh*Ww)
#define CHW (Cc*HW)

// GEMM tile geometry
#define RS 40              // smem row stride in bf16 elems (80B, 16B-aligned, conflict-free ldsm)
#define APL (128*RS)       // A plane elems
#define BPL (64*RS)        // B plane elems
#define SMEMB ((4*APL + 4*BPL) * 2)   // total dynamic smem bytes = 61440

// ---------------- device scratch ----------------
__device__ float g_x[Bb*CHW];
__device__ float g_y[Bb*CHW];
__device__ float g_t[Bb*CHW];
__device__ float g_mean[Bb*HW];
__device__ float g_inv[Bb*HW];
__device__ float g_q1[Bb*Nq*HID];
__device__ float g_q2[Bb*Nq*HID];
__device__ float g_q4[Bb*Nq*IDim];
__device__ float g_qq[Bb*Nq*Cc];
__device__ float g_off[Bb*Nq];
__device__ float g_m[Bb*Nq*HW];

__device__ __forceinline__ float gelu_f(float x) {
    return 0.5f * x * (1.0f + erff(x * 0.70710678118654752f));
}
__device__ __forceinline__ uint32_t su32(const void* p) {
    return (uint32_t)__cvta_generic_to_shared(p);
}
__device__ __forceinline__ void ldsm4(uint32_t* r, uint32_t addr) {
    asm volatile("ldmatrix.sync.aligned.m8n8.x4.shared.b16 {%0,%1,%2,%3}, [%4];"
        : "=r"(r[0]), "=r"(r[1]), "=r"(r[2]), "=r"(r[3]) : "r"(addr));
}
__device__ __forceinline__ void mma16816(float* d, const uint32_t* a, const uint32_t* b) {
    asm volatile("mma.sync.aligned.m16n8k16.row.col.f32.bf16.bf16.f32 "
        "{%0,%1,%2,%3}, {%4,%5,%6,%7}, {%8,%9}, {%0,%1,%2,%3};"
        : "+f"(d[0]), "+f"(d[1]), "+f"(d[2]), "+f"(d[3])
        : "r"(a[0]), "r"(a[1]), "r"(a[2]), "r"(a[3]), "r"(b[0]), "r"(b[1]));
}
__device__ __forceinline__ void split_bf16(float x, __nv_bfloat16& hi, __nv_bfloat16& lo) {
    hi = __float2bfloat16(x);
    lo = __float2bfloat16(x - __bfloat162float(hi));
}
__device__ __forceinline__ uint32_t pk2(__nv_bfloat16 a, __nv_bfloat16 b) {
    __nv_bfloat162 t(a, b);
    uint32_t u;
    memcpy(&u, &t, 4);
    return u;
}

// ---------------- depthwise 3x3 conv (SAME) + bias ----------------
__global__ void dw_kernel(const float* __restrict__ x, const float* __restrict__ w,
                          const float* __restrict__ bia, float* __restrict__ out)
{
    int wq = threadIdx.x;
    int hq = blockIdx.y * 4 + threadIdx.y;
    int plane = blockIdx.z;
    int c = plane & (Cc - 1);
    const float* xp = x + (long)plane * HW;
    const float* wp = w + c * 9;
    float w00 = wp[0], w01 = wp[1], w02 = wp[2];
    float w10 = wp[3], w11 = wp[4], w12 = wp[5];
    float w20 = wp[6], w21 = wp[7], w22 = wp[8];
    float acc = bia[c];

    const float* r0 = xp + (hq - 1) * Ww;
    const float* r1 = xp + hq * Ww;
    const float* r2 = xp + (hq + 1) * Ww;
    bool ht = hq > 0, hb = hq < Hh - 1;
    bool wl = wq > 0, wr = wq < Ww - 1;

    if (ht) {
        if (wl) acc += w00 * r0[wq - 1];
        acc += w01 * r0[wq];
        if (wr) acc += w02 * r0[wq + 1];
    }
    {
        if (wl) acc += w10 * r1[wq - 1];
        acc += w11 * r1[wq];
        if (wr) acc += w12 * r1[wq + 1];
    }
    if (hb) {
        if (wl) acc += w20 * r2[wq - 1];
        acc += w21 * r2[wq];
        if (wr) acc += w22 * r2[wq + 1];
    }
    out[(long)plane * HW + hq * Ww + wq] = acc;
}

// ---------------- LN stats per pixel ----------------
__global__ void stats_kernel(const float* __restrict__ t,
                             float* __restrict__ mean, float* __restrict__ inv)
{
    int p = blockIdx.x * blockDim.x + threadIdx.x;
    if (p >= Bb*HW) return;
    int bb = p / HW;
    int pix = p - bb * HW;
    const float* base = t + (long)bb * CHW + pix;
    float s = 0.f, s2 = 0.f;
#pragma unroll 8
    for (int c = 0; c < Cc; c++) {
        float v = base[(long)c * HW];
        s += v; s2 += v * v;
    }
    float m = s * (1.0f / Cc);
    float var = s2 * (1.0f / Cc) - m * m;
    mean[p] = m;
    inv[p] = rsqrtf(var + 1e-6f);
}

// ---------------- tensor-core GEMM (bf16 3-pass split), BK=32 ----------------
// BM=128, BN=64. 8 warps (4m x 2n), warp tile 32x32.
template<int ACT, int BMODE, int BIASM, bool LNF, bool RES>
__global__ void __launch_bounds__(256, 2)
gemm_tc(const float* __restrict__ A, const float* __restrict__ B,
        const float* __restrict__ bias, const float* __restrict__ resid,
        const float* __restrict__ lnMean, const float* __restrict__ lnInv,
        const float* __restrict__ lnW, const float* __restrict__ lnB,
        float* __restrict__ C, int M, int N, int K,
        long sA, long sB, long sC)
{
    extern __shared__ __align__(16) __nv_bfloat16 dsm[];
    // A planes: (buf*2+split)*APL ; B planes: 4*APL + (buf*2+split)*BPL

    int z = blockIdx.z;
    A += z * sA; B += z * sB; C += z * sC;
    const float* R = RES ? (resid + z * sC) : nullptr;

    int m0 = blockIdx.y * 128;
    int n0 = blockIdx.x * 64;

    int tid = threadIdx.x;
    int warp = tid >> 5;
    int lane = tid & 31;
    int wm = warp & 3;
    int wn = warp >> 2;

    // loader indices (BK=32)
    int arow = tid >> 1;
    int acol = (tid & 1) * 16;            // 0 or 16
    int brow = tid >> 2;                  // 0..63 (n)
    int bcol = (tid & 3) * 8;             // 0,8,16,24 (k)

    float mea = 0.f, iva = 0.f;
    if (LNF) {
        mea = lnMean[(long)z * N + n0 + brow];
        iva = lnInv [(long)z * N + n0 + brow];
    }

    float acc[2][4][4];
#pragma unroll
    for (int i = 0; i < 2; i++)
#pragma unroll
        for (int j = 0; j < 4; j++)
#pragma unroll
            for (int q = 0; q < 4; q++) acc[i][j][q] = 0.f;

    const int KT = K >> 5;
    int gm_ld = m0 + arow;
    bool mok = gm_ld < M;
    const float* Aip = A + (long)gm_ld * K + acol;

    float4 pa[4];
    float bv[8];

    // ---- helpers as macros via lambdas ----
    auto loadTile = [&](int kb) {
#pragma unroll
        for (int j = 0; j < 4; j++)
            pa[j] = mok ? *(const float4*)(Aip + kb + j*4) : make_float4(0,0,0,0);
        if (BMODE == 1) {
            const float* Bp = B + (long)(n0 + brow) * K + kb + bcol;
            float4 pb0 = *(const float4*)(Bp + 0);
            float4 pb1 = *(const float4*)(Bp + 4);
            bv[0]=pb0.x; bv[1]=pb0.y; bv[2]=pb0.z; bv[3]=pb0.w;
            bv[4]=pb1.x; bv[5]=pb1.y; bv[6]=pb1.z; bv[7]=pb1.w;
        } else {
            const float* Bp = B + (long)(kb + bcol) * N + n0 + brow;
#pragma unroll
            for (int j = 0; j < 8; j++) bv[j] = Bp[(long)j * N];
            if (LNF) {
#pragma unroll
                for (int j = 0; j < 8; j++)
                    bv[j] = (bv[j] - mea) * iva * lnW[kb + bcol + j] + lnB[kb + bcol + j];
            }
        }
    };
    auto storeTile = [&](int buf) {
        __nv_bfloat16 h[16], l[16];
        float v[16] = {pa[0].x,pa[0].y,pa[0].z,pa[0].w, pa[1].x,pa[1].y,pa[1].z,pa[1].w,
                       pa[2].x,pa[2].y,pa[2].z,pa[2].w, pa[3].x,pa[3].y,pa[3].z,pa[3].w};
#pragma unroll
        for (int j = 0; j < 16; j++) split_bf16(v[j], h[j], l[j]);
        __nv_bfloat16* A0 = dsm + (buf*2+0)*APL + arow*RS + acol;
        __nv_bfloat16* A1 = dsm + (buf*2+1)*APL + arow*RS + acol;
        *(uint4*)(A0)     = make_uint4(pk2(h[0],h[1]),  pk2(h[2],h[3]),  pk2(h[4],h[5]),  pk2(h[6],h[7]));
        *(uint4*)(A0 + 8) = make_uint4(pk2(h[8],h[9]),  pk2(h[10],h[11]),pk2(h[12],h[13]),pk2(h[14],h[15]));
        *(uint4*)(A1)     = make_uint4(pk2(l[0],l[1]),  pk2(l[2],l[3]),  pk2(l[4],l[5]),  pk2(l[6],l[7]));
        *(uint4*)(A1 + 8) = make_uint4(pk2(l[8],l[9]),  pk2(l[10],l[11]),pk2(l[12],l[13]),pk2(l[14],l[15]));
        __nv_bfloat16 bh[8], bl[8];
#pragma unroll
        for (int j = 0; j < 8; j++) split_bf16(bv[j], bh[j], bl[j]);
        __nv_bfloat16* B0 = dsm + 4*APL + (buf*2+0)*BPL + brow*RS + bcol;
        __nv_bfloat16* B1 = dsm + 4*APL + (buf*2+1)*BPL + brow*RS + bcol;
        *(uint4*)(B0) = make_uint4(pk2(bh[0],bh[1]), pk2(bh[2],bh[3]), pk2(bh[4],bh[5]), pk2(bh[6],bh[7]));
        *(uint4*)(B1) = make_uint4(pk2(bl[0],bl[1]), pk2(bl[2],bl[3]), pk2(bl[4],bl[5]), pk2(bl[6],bl[7]));
    };

    // ---- prologue ----
    loadTile(0);
    storeTile(0);
    __syncthreads();

    int a_mrow = lane & 15;
    int a_kh = (lane >> 4) * 8;
    int b_row = ((lane >> 4) & 1) * 8 + (lane & 7);
    int b_kh = ((lane >> 3) & 1) * 8;

    for (int kt = 0; kt < KT; kt++) {
        int buf = kt & 1;
        if (kt + 1 < KT) loadTile((kt + 1) << 5);

        const __nv_bfloat16* Ah = dsm + (buf*2+0)*APL;
        const __nv_bfloat16* Al = dsm + (buf*2+1)*APL;
        const __nv_bfloat16* Bh = dsm + 4*APL + (buf*2+0)*BPL;
        const __nv_bfloat16* Bl = dsm + 4*APL + (buf*2+1)*BPL;

#pragma unroll
        for (int half = 0; half < 2; half++) {
            int kc = half * 16;
            uint32_t afr[2][2][4];
#pragma unroll
            for (int s = 0; s < 2; s++) {
                const __nv_bfloat16* Ap = s ? Al : Ah;
#pragma unroll
                for (int mt = 0; mt < 2; mt++) {
                    uint32_t addr = su32(Ap + (wm*32 + mt*16 + a_mrow) * RS + kc + a_kh);
                    ldsm4(afr[s][mt], addr);
                }
            }
#pragma unroll
            for (int p = 0; p < 2; p++) {
                uint32_t bb0[4], bb1[4];
                ldsm4(bb0, su32(Bh + (wn*32 + p*16 + b_row) * RS + kc + b_kh));
                ldsm4(bb1, su32(Bl + (wn*32 + p*16 + b_row) * RS + kc + b_kh));
#pragma unroll
                for (int mt = 0; mt < 2; mt++) {
                    mma16816(acc[mt][2*p],   afr[0][mt], bb0);
                    mma16816(acc[mt][2*p],   afr[0][mt], bb1);
                    mma16816(acc[mt][2*p],   afr[1][mt], bb0);
                    mma16816(acc[mt][2*p+1], afr[0][mt], bb0 + 2);
                    mma16816(acc[mt][2*p+1], afr[0][mt], bb1 + 2);
                    mma16816(acc[mt][2*p+1], afr[1][mt], bb0 + 2);
                }
            }
        }

        if (kt + 1 < KT) {
            __syncthreads();       // ensure all warps done reading buf^1 from prev iter? (buf reuse)
            storeTile(buf ^ 1);
            __syncthreads();
        }
    }

    // ---- epilogue ----
#pragma unroll
    for (int mt = 0; mt < 2; mt++) {
#pragma unroll
        for (int nt = 0; nt < 4; nt++) {
            int gn = n0 + wn*32 + nt*8 + (lane & 3) * 2;
            float bn0v = 0.f, bn1v = 0.f;
            if (BIASM == 2) { bn0v = bias[gn]; bn1v = bias[gn + 1]; }
#pragma unroll
            for (int h = 0; h < 2; h++) {
                int row = m0 + wm*32 + mt*16 + (lane >> 2) + h*8;
                if (row >= M) continue;
                float x0 = acc[mt][nt][h*2 + 0];
                float x1 = acc[mt][nt][h*2 + 1];
                if (BIASM == 1) { float bm = bias[row]; x0 += bm; x1 += bm; }
                if (BIASM == 2) { x0 += bn0v; x1 += bn1v; }
                if (ACT == 1) { x0 = fmaxf(x0, 0.f); x1 = fmaxf(x1, 0.f); }
                if (ACT == 2) { x0 = gelu_f(x0); x1 = gelu_f(x1); }
                if (RES) {
                    float2 r2 = *(const float2*)&R[(long)row * N + gn];
                    x0 += r2.x; x1 += r2.y;
                }
                float2 o; o.x = x0; o.y = x1;
                *(float2*)&C[(long)row * N + gn] = o;
            }
        }
    }
}

// ---------------- per-query offset ----------------
__global__ void off_kernel(const float* __restrict__ q4, const float* __restrict__ sb,
                           const float* __restrict__ hb, float* __restrict__ off)
{
    int n = blockIdx.x * blockDim.x + threadIdx.x;
    if (n >= Bb*Nq) return;
    float s = hb[0];
#pragma unroll 8
    for (int i = 0; i < IDim; i++) s += q4[(long)n * IDim + i] * sb[i];
    off[n] = s;
}

// ---------------- bilinear 2x upsample + offset ----------------
__global__ void upsample_kernel(const float* __restrict__ m, const float* __restrict__ off,
                                float* __restrict__ out)
{
    long idx = (long)blockIdx.x * blockDim.x + threadIdx.x;
    const long tot4 = (long)Bb * Nq * H2 * (W2 / 4);
    if (idx >= tot4) return;
    int wq4 = (int)(idx % (W2 / 4)) * 4;
    int h2 = (int)((idx / (W2 / 4)) % H2);
    long bn = idx / ((long)(W2 / 4) * H2);

    float fh = h2 * 0.5f - 0.25f;
    int h0f = (int)floorf(fh);
    float wh = fh - (float)h0f;
    int h0 = max(h0f, 0), h1 = min(h0f + 1, Hh - 1);

    const float* r0 = m + bn * (long)HW + h0 * Ww;
    const float* r1 = m + bn * (long)HW + h1 * Ww;
    float o = off[bn];

    float r[4];
#pragma unroll
    for (int j = 0; j < 4; j++) {
        int w2 = wq4 + j;
        float fw = w2 * 0.5f - 0.25f;
        int w0f = (int)floorf(fw);
        float ww = fw - (float)w0f;
        int w0 = max(w0f, 0), w1 = min(w0f + 1, Ww - 1);
        float t0 = r0[w0] * (1.f - ww) + r0[w1] * ww;
        float t1 = r1[w0] * (1.f - ww) + r1[w1] * ww;
        r[j] = t0 * (1.f - wh) + t1 * wh + o;
    }
    float4 v = make_float4(r[0], r[1], r[2], r[3]);
    *(float4*)(out + bn * (long)(H2 * W2) + (long)h2 * W2 + wq4) = v;
}

// ---------------- launcher ----------------
extern "C" void kernel_launch(void* const* d_in, const int* in_sizes, int n_in,
                              void* d_out, int out_size)
{
    const float* spat    = (const float*)d_in[0];
    const float* qf      = (const float*)d_in[1];
    const float* dw_w    = (const float*)d_in[2];
    const float* dw_b    = (const float*)d_in[3];
    const float* ln_w    = (const float*)d_in[4];
    const float* ln_b    = (const float*)d_in[5];
    const float* pw_w    = (const float*)d_in[6];
    const float* pw_b    = (const float*)d_in[7];
    const float* sproj_w = (const float*)d_in[8];
    const float* sproj_b = (const float*)d_in[9];
    const float* mlp_w1  = (const float*)d_in[10];
    const float* mlp_b1  = (const float*)d_in[11];
    const float* mlp_w2  = (const float*)d_in[12];
    const float* mlp_b2  = (const float*)d_in[13];
    const float* mlp_w3  = (const float*)d_in[14];
    const float* mlp_b3  = (const float*)d_in[15];
    const float* qproj_w = (const float*)d_in[16];
    const float* qproj_b = (const float*)d_in[17];
    const float* head_b  = (const float*)d_in[18];
    float* out = (float*)d_out;

    float *px, *py, *pt, *pmean, *pinv, *pq1, *pq2, *pq4, *pqq, *poff, *pm;
    cudaGetSymbolAddress((void**)&px,    g_x);
    cudaGetSymbolAddress((void**)&py,    g_y);
    cudaGetSymbolAddress((void**)&pt,    g_t);
    cudaGetSymbolAddress((void**)&pmean, g_mean);
    cudaGetSymbolAddress((void**)&pinv,  g_inv);
    cudaGetSymbolAddress((void**)&pq1,   g_q1);
    cudaGetSymbolAddress((void**)&pq2,   g_q2);
    cudaGetSymbolAddress((void**)&pq4,   g_q4);
    cudaGetSymbolAddress((void**)&pqq,   g_qq);
    cudaGetSymbolAddress((void**)&poff,  g_off);
    cudaGetSymbolAddress((void**)&pm,    g_m);

    // raise dynamic smem cap for every instantiation we use (idempotent, capture-safe)
    cudaFuncSetAttribute(gemm_tc<1,1,2,false,false>, cudaFuncAttributeMaxDynamicSharedMemorySize, SMEMB);
    cudaFuncSetAttribute(gemm_tc<2,0,1,true,true>,   cudaFuncAttributeMaxDynamicSharedMemorySize, SMEMB);
    cudaFuncSetAttribute(gemm_tc<0,1,2,false,false>, cudaFuncAttributeMaxDynamicSharedMemorySize, SMEMB);
    cudaFuncSetAttribute(gemm_tc<0,0,0,false,false>, cudaFuncAttributeMaxDynamicSharedMemorySize, SMEMB);

    dim3 dwBlock(80, 4);
    dim3 dwGrid(1, Hh / 4, Bb * Cc);
    const int pix = Bb * HW;
    const int Mq = Bb * Nq;

    // Launch #1..#3: dw0, stats0, mlp1 (independent)
    dw_kernel<<<dwGrid, dwBlock>>>(spat, dw_w, dw_b, pt);
    stats_kernel<<<(pix + 255)/256, 256>>>(pt, pmean, pinv);
    gemm_tc<1, 1, 2, false, false><<<dim3(HID / 64, (Mq + 127) / 128, 1), 256, SMEMB>>>(
        qf, mlp_w1, mlp_b1, nullptr, nullptr, nullptr, nullptr, nullptr,
        pq1, Mq, HID, Cc, 0, 0, 0);

    // Launch #4: pw GEMM block0 (profiling target)
    gemm_tc<2, 0, 1, true, true><<<dim3(HW / 64, 2, Bb), 256, SMEMB>>>(
        pw_w, pt, pw_b, spat, pmean, pinv, ln_w, ln_b,
        px, Cc, HW, Cc, 0, CHW, CHW);

    // ---- spatial block 1 ----
    dw_kernel<<<dwGrid, dwBlock>>>(px, dw_w + Cc * 9, dw_b + Cc, pt);
    stats_kernel<<<(pix + 255)/256, 256>>>(pt, pmean, pinv);
    gemm_tc<2, 0, 1, true, true><<<dim3(HW / 64, 2, Bb), 256, SMEMB>>>(
        pw_w + Cc * Cc, pt, pw_b + Cc, px, pmean, pinv, ln_w + Cc, ln_b + Cc,
        py, Cc, HW, Cc, 0, CHW, CHW);

    // ---- rest of query MLP chain ----
    gemm_tc<1, 1, 2, false, false><<<dim3(HID / 64, (Mq + 127) / 128, 1), 256, SMEMB>>>(
        pq1, mlp_w2, mlp_b2, nullptr, nullptr, nullptr, nullptr, nullptr,
        pq2, Mq, HID, HID, 0, 0, 0);
    gemm_tc<0, 1, 2, false, false><<<dim3(Cc / 64, (Mq + 127) / 128, 1), 256, SMEMB>>>(
        pq2, mlp_w3, mlp_b3, nullptr, nullptr, nullptr, nullptr, nullptr,
        pq1, Mq, Cc, HID, 0, 0, 0);
    gemm_tc<0, 1, 2, false, false><<<dim3(IDim / 64, (Mq + 127) / 128, 1), 256, SMEMB>>>(
        pq1, qproj_w, qproj_b, nullptr, nullptr, nullptr, nullptr, nullptr,
        pq4, Mq, IDim, Cc, 0, 0, 0);
    gemm_tc<0, 0, 0, false, false><<<dim3(Cc / 64, (Mq + 127) / 128, 1), 256, SMEMB>>>(
        pq4, sproj_w, nullptr, nullptr, nullptr, nullptr, nullptr, nullptr,
        pqq, Mq, Cc, IDim, 0, 0, 0);
    off_kernel<<<(Mq + 255)/256, 256>>>(pq4, sproj_b, head_b, poff);

    // ---- mask GEMM at 80x80 ----
    gemm_tc<0, 0, 0, false, false><<<dim3(HW / 64, (Nq + 127) / 128, Bb), 256, SMEMB>>>(
        pqq, py, nullptr, nullptr, nullptr, nullptr, nullptr, nullptr,
        pm, Nq, HW, Cc, (long)Nq * Cc, (long)CHW, (long)Nq * HW);

    // ---- bilinear 2x upsample + per-(b,n) offset ----
    const long tot4 = (long)Bb * Nq * H2 * (W2 / 4);
    upsample_kernel<<<(unsigned)((tot4 + 255)/256), 256>>>(pm, poff, out);
}

// round 10
// speedup vs baseline: 1.2684x; 1.0045x over previous
#include <cuda_runtime.h>
#include <cuda_bf16.h>
#include <math.h>
#include <stdint.h>
#include <string.h>

// ---------------- problem constants ----------------
#define Bb 4
#define Cc 256
#define Hh 80
#define Ww 80
#define Nq 300
#define IDim 128
#define HID 512
#define H2 160
#define W2 160
#define HW (Hh*Ww)
#define CHW (Cc*HW)

// ---------------- GEMM tile geometry ----------------
// BM=128, BN=64, BK=32, 3-stage cp.async pipeline.
// A smem rows: 32 bf16 = 64B data, stride 80B (RS=40 elems).
// B smem rows (k-major): 64 bf16 = 128B data, stride 144B (RSB=72 elems).
#define RS 40
#define RSB 72
#define A_PL 10240                  // bytes per A plane (128*80)
#define B_PL 4608                   // bytes per B plane (32*144)
#define STG_A_H 0
#define STG_A_L 10240
#define STG_B_H 20480
#define STG_B_L 25088
#define STG_SZ 29696
#define SMEMB (3*STG_SZ)            // 89088

// ---------------- device scratch (f32) ----------------
__device__ float g_x[Bb*CHW];        // block0 output
__device__ float g_t[Bb*CHW];        // dw temp
__device__ float g_q4[Bb*Nq*IDim];
__device__ float g_off[Bb*Nq];
__device__ float g_m[Bb*Nq*HW];

// ---------------- device scratch (bf16 hi/lo planes) ----------------
__device__ __nv_bfloat16 g_pwh[2*Cc*Cc],  g_pwl[2*Cc*Cc];    // pw weights, A-layout [cout][cin]
__device__ __nv_bfloat16 g_w1h[Cc*HID],   g_w1l[Cc*HID];     // w1^T  [256][512]
__device__ __nv_bfloat16 g_w2h[HID*HID],  g_w2l[HID*HID];    // w2^T  [512][512]
__device__ __nv_bfloat16 g_w3h[HID*Cc],   g_w3l[HID*Cc];     // w3^T  [512][256]
__device__ __nv_bfloat16 g_qph[Cc*IDim],  g_qpl[Cc*IDim];    // qproj^T [256][128]
__device__ __nv_bfloat16 g_sph[IDim*Cc],  g_spl[IDim*Cc];    // sproj  [128][256] (natural)
__device__ __nv_bfloat16 g_qfh[Bb*Nq*Cc], g_qfl[Bb*Nq*Cc];
__device__ __nv_bfloat16 g_o1h[Bb*Nq*HID],g_o1l[Bb*Nq*HID];
__device__ __nv_bfloat16 g_o2h[Bb*Nq*HID],g_o2l[Bb*Nq*HID];
__device__ __nv_bfloat16 g_o3h[Bb*Nq*Cc], g_o3l[Bb*Nq*Cc];
__device__ __nv_bfloat16 g_o4h[Bb*Nq*IDim],g_o4l[Bb*Nq*IDim];
__device__ __nv_bfloat16 g_qqh[Bb*Nq*Cc], g_qql[Bb*Nq*Cc];
__device__ __nv_bfloat16 g_bsh[Bb*CHW],   g_bsl[Bb*CHW];     // LN'd spatial [c][pix]
__device__ __nv_bfloat16 g_ysh[Bb*CHW],   g_ysl[Bb*CHW];     // y planes [c][pix]

__device__ __forceinline__ float gelu_f(float x) {
    return 0.5f * x * (1.0f + erff(x * 0.70710678118654752f));
}
__device__ __forceinline__ uint32_t su32(const void* p) {
    return (uint32_t)__cvta_generic_to_shared(p);
}
__device__ __forceinline__ void ldsm4(uint32_t* r, uint32_t addr) {
    asm volatile("ldmatrix.sync.aligned.m8n8.x4.shared.b16 {%0,%1,%2,%3}, [%4];"
        : "=r"(r[0]), "=r"(r[1]), "=r"(r[2]), "=r"(r[3]) : "r"(addr));
}
__device__ __forceinline__ void ldsm4t(uint32_t* r, uint32_t addr) {
    asm volatile("ldmatrix.sync.aligned.m8n8.x4.trans.shared.b16 {%0,%1,%2,%3}, [%4];"
        : "=r"(r[0]), "=r"(r[1]), "=r"(r[2]), "=r"(r[3]) : "r"(addr));
}
__device__ __forceinline__ void mma16816(float* d, const uint32_t* a, const uint32_t* b) {
    asm volatile("mma.sync.aligned.m16n8k16.row.col.f32.bf16.bf16.f32 "
        "{%0,%1,%2,%3}, {%4,%5,%6,%7}, {%8,%9}, {%0,%1,%2,%3};"
        : "+f"(d[0]), "+f"(d[1]), "+f"(d[2]), "+f"(d[3])
        : "r"(a[0]), "r"(a[1]), "r"(a[2]), "r"(a[3]), "r"(b[0]), "r"(b[1]));
}
__device__ __forceinline__ void split_bf16(float x, __nv_bfloat16& hi, __nv_bfloat16& lo) {
    hi = __float2bfloat16(x);
    lo = __float2bfloat16(x - __bfloat162float(hi));
}
__device__ __forceinline__ uint32_t pk2(__nv_bfloat16 a, __nv_bfloat16 b) {
    __nv_bfloat162 t(a, b);
    uint32_t u;
    memcpy(&u, &t, 4);
    return u;
}
__device__ __forceinline__ void cpa16(uint32_t d, const void* s, int bytes) {
    asm volatile("cp.async.cg.shared.global [%0], [%1], 16, %2;"
        :: "r"(d), "l"(s), "r"(bytes));
}
#define CP_COMMIT asm volatile("cp.async.commit_group;")
#define CP_WAIT1  asm volatile("cp.async.wait_group 1;")

// ---------------- depthwise 3x3 conv (SAME) + bias ----------------
__global__ void dw_kernel(const float* __restrict__ x, const float* __restrict__ w,
                          const float* __restrict__ bia, float* __restrict__ out)
{
    int wq = threadIdx.x;
    int hq = blockIdx.y * 4 + threadIdx.y;
    int plane = blockIdx.z;
    int c = plane & (Cc - 1);
    const float* xp = x + (long)plane * HW;
    const float* wp = w + c * 9;
    float w00 = wp[0], w01 = wp[1], w02 = wp[2];
    float w10 = wp[3], w11 = wp[4], w12 = wp[5];
    float w20 = wp[6], w21 = wp[7], w22 = wp[8];
    float acc = bia[c];

    const float* r0 = xp + (hq - 1) * Ww;
    const float* r1 = xp + hq * Ww;
    const float* r2 = xp + (hq + 1) * Ww;
    bool ht = hq > 0, hb = hq < Hh - 1;
    bool wl = wq > 0, wr = wq < Ww - 1;

    if (ht) {
        if (wl) acc += w00 * r0[wq - 1];
        acc += w01 * r0[wq];
        if (wr) acc += w02 * r0[wq + 1];
    }
    {
        if (wl) acc += w10 * r1[wq - 1];
        acc += w11 * r1[wq];
        if (wr) acc += w12 * r1[wq + 1];
    }
    if (hb) {
        if (wl) acc += w20 * r2[wq - 1];
        acc += w21 * r2[wq];
        if (wr) acc += w22 * r2[wq + 1];
    }
    out[(long)plane * HW + hq * Ww + wq] = acc;
}

// ---------------- LN stats + apply + split, [c][pix] planes ----------------
__global__ void stats_kernel(const float* __restrict__ t,
                             const float* __restrict__ lw, const float* __restrict__ lb,
                             __nv_bfloat16* __restrict__ oh, __nv_bfloat16* __restrict__ ol)
{
    int p = blockIdx.x * blockDim.x + threadIdx.x;
    if (p >= Bb*HW) return;
    int bb = p / HW;
    int pix = p - bb * HW;
    const float* base = t + (long)bb * CHW + pix;
    float s = 0.f, s2 = 0.f;
#pragma unroll 8
    for (int c = 0; c < Cc; c++) {
        float v = base[(long)c * HW];
        s += v; s2 += v * v;
    }
    float m = s * (1.0f / Cc);
    float var = s2 * (1.0f / Cc) - m * m;
    float inv = rsqrtf(var + 1e-6f);

    __nv_bfloat16* po = oh + (long)bb * CHW + pix;
    __nv_bfloat16* pl = ol + (long)bb * CHW + pix;
#pragma unroll 4
    for (int c = 0; c < Cc; c++) {
        float v = (base[(long)c * HW] - m) * inv * lw[c] + lb[c];
        __nv_bfloat16 h, l;
        split_bf16(v, h, l);
        po[(long)c * HW] = h;
        pl[(long)c * HW] = l;
    }
}

// ---------------- elementwise split f32 -> bf16 hi/lo ----------------
__global__ void split_k(const float* __restrict__ src,
                        __nv_bfloat16* __restrict__ hi, __nv_bfloat16* __restrict__ lo,
                        int n4)
{
    int i = blockIdx.x * blockDim.x + threadIdx.x;
    if (i >= n4) return;
    float4 v = ((const float4*)src)[i];
    __nv_bfloat16 h0,l0,h1,l1,h2,l2,h3,l3;
    split_bf16(v.x,h0,l0); split_bf16(v.y,h1,l1);
    split_bf16(v.z,h2,l2); split_bf16(v.w,h3,l3);
    ((uint32_t*)hi)[i*2]   = pk2(h0,h1);
    ((uint32_t*)hi)[i*2+1] = pk2(h2,h3);
    ((uint32_t*)lo)[i*2]   = pk2(l0,l1);
    ((uint32_t*)lo)[i*2+1] = pk2(l2,l3);
}

// ---------------- transpose + split: X[Krows x Ncols] -> O[Ncols x Krows] ----------------
__global__ void splitT_k(const float* __restrict__ X,
                         __nv_bfloat16* __restrict__ Oh, __nv_bfloat16* __restrict__ Ol,
                         int Krows, int Ncols)
{
    int z = blockIdx.z;
    long zoff = (long)z * Krows * Ncols;
    X += zoff; Oh += zoff; Ol += zoff;

    __shared__ float ts[32][33];
    int n0 = blockIdx.x * 32, k0 = blockIdx.y * 32;
    int tx = threadIdx.x, ty = threadIdx.y;   // (32, 8)

#pragma unroll
    for (int j = 0; j < 4; j++)
        ts[ty + j*8][tx] = X[(long)(k0 + ty + j*8) * Ncols + n0 + tx];
    __syncthreads();

#pragma unroll
    for (int j = 0; j < 4; j++) {
        int n = n0 + ty + j*8;
        int k = k0 + tx;
        float v = ts[tx][ty + j*8];
        __nv_bfloat16 h, l;
        split_bf16(v, h, l);
        Oh[(long)n * Krows + k] = h;
        Ol[(long)n * Krows + k] = l;
    }
}

// ---------------- bf16 tensor-core GEMM, pre-split streaming ----------------
// C[m,n] = act( sum_k A[m,k]*B[k,n] + bias ) (+ resid)
// A: [M][K] hi/lo bf16; B: [K][N] hi/lo bf16. 3 passes hi*hi+hi*lo+lo*hi.
// OUTF: write f32 C. OUTS: write split planes Oh/Ol (C layout).
template<int ACT, int BIASM, bool RES, bool OUTF, bool OUTS>
__global__ void __launch_bounds__(256, 2)
gemm_ps(const __nv_bfloat16* __restrict__ Ah_g, const __nv_bfloat16* __restrict__ Al_g,
        const __nv_bfloat16* __restrict__ Bh_g, const __nv_bfloat16* __restrict__ Bl_g,
        const float* __restrict__ bias, const float* __restrict__ resid,
        float* __restrict__ C, __nv_bfloat16* __restrict__ Oh, __nv_bfloat16* __restrict__ Ol,
        int M, int N, int K, long sA, long sB, long sC)
{
    extern __shared__ __align__(16) char dsm[];
    uint32_t sb = su32(dsm);

    int z = blockIdx.z;
    Ah_g += z * sA; Al_g += z * sA;
    Bh_g += z * sB; Bl_g += z * sB;
    if (OUTF) C += z * sC;
    if (OUTS) { Oh += z * sC; Ol += z * sC; }
    const float* R = RES ? (resid + z * sC) : nullptr;

    int m0 = blockIdx.y * 128;
    int n0 = blockIdx.x * 64;
    int tid = threadIdx.x;
    int warp = tid >> 5;
    int lane = tid & 31;
    int wm = warp & 3;
    int wn = warp >> 2;

    // loader indices
    int a_r = tid >> 1;                 // 0..127 m-row (2 chunks per row handled by i loop)
    int a_c = (tid & 1) * 2;            // chunk pair base: c8 in {0,1} or {2,3}
    int b_r = tid >> 3;                 // 0..31 k-row
    int b_c = tid & 7;                  // 0..7 16B chunk in row

    const int KT = K >> 5;

    auto loadStage = [&](int st, int kb) {
        uint32_t abase = sb + st * STG_SZ;
        // A: hi/lo, 2 chunks each per thread
        bool mok = (m0 + a_r) < M;
        int ab = mok ? 16 : 0;
        const __nv_bfloat16* sh = Ah_g + (long)(m0 + a_r) * K + kb;
        const __nv_bfloat16* sl = Al_g + (long)(m0 + a_r) * K + kb;
        uint32_t dA = abase + a_r * 80 + a_c * 16;
#pragma unroll
        for (int j = 0; j < 2; j++) {
            cpa16(dA + STG_A_H + j * 16, sh + (a_c + j) * 8, ab);
            cpa16(dA + STG_A_L + j * 16, sl + (a_c + j) * 8, ab);
        }
        // B: hi/lo, 1 chunk each per thread
        const __nv_bfloat16* bh = Bh_g + (long)(kb + b_r) * N + n0 + b_c * 8;
        const __nv_bfloat16* bl = Bl_g + (long)(kb + b_r) * N + n0 + b_c * 8;
        uint32_t dB = abase + b_r * 144 + b_c * 16;
        cpa16(dB + STG_B_H, bh, 16);
        cpa16(dB + STG_B_L, bl, 16);
    };

    // prologue: stages 0,1
    loadStage(0, 0);
    CP_COMMIT;
    if (KT > 1) loadStage(1, 32);
    CP_COMMIT;

    float acc[2][4][4];
#pragma unroll
    for (int i = 0; i < 2; i++)
#pragma unroll
        for (int j = 0; j < 4; j++)
#pragma unroll
            for (int q = 0; q < 4; q++) acc[i][j][q] = 0.f;

    int a_mrow = lane & 15;
    int a_kh = (lane >> 4) * 8;
    int bg = lane >> 3;
    int b_kr = (bg & 1) * 8 + (lane & 7);
    int b_nc = (bg >> 1) * 8;

    int st = 0;
    for (int kt = 0; kt < KT; kt++) {
        CP_WAIT1;
        __syncthreads();
        if (kt + 2 < KT) loadStage((st + 2 >= 3) ? st - 1 : st + 2, (kt + 2) << 5);
        CP_COMMIT;

        uint32_t base = sb + st * STG_SZ;
#pragma unroll
        for (int half = 0; half < 2; half++) {
            int kc = half * 16;
            uint32_t afr[2][2][4];
#pragma unroll
            for (int s = 0; s < 2; s++) {
                uint32_t ap = base + (s ? STG_A_L : STG_A_H);
#pragma unroll
                for (int mt = 0; mt < 2; mt++) {
                    ldsm4(afr[s][mt], ap + ((wm*32 + mt*16 + a_mrow) * RS + kc + a_kh) * 2);
                }
            }
#pragma unroll
            for (int p = 0; p < 2; p++) {
                uint32_t bb0[4], bb1[4];
                uint32_t boff = ((kc + b_kr) * RSB + wn*32 + p*16 + b_nc) * 2;
                ldsm4t(bb0, base + STG_B_H + boff);
                ldsm4t(bb1, base + STG_B_L + boff);
#pragma unroll
                for (int mt = 0; mt < 2; mt++) {
                    mma16816(acc[mt][2*p],   afr[0][mt], bb0);
                    mma16816(acc[mt][2*p],   afr[0][mt], bb1);
                    mma16816(acc[mt][2*p],   afr[1][mt], bb0);
                    mma16816(acc[mt][2*p+1], afr[0][mt], bb0 + 2);
                    mma16816(acc[mt][2*p+1], afr[0][mt], bb1 + 2);
                    mma16816(acc[mt][2*p+1], afr[1][mt], bb0 + 2);
                }
            }
        }
        st++;
        if (st == 3) st = 0;
    }

    // ---- epilogue ----
#pragma unroll
    for (int mt = 0; mt < 2; mt++) {
#pragma unroll
        for (int nt = 0; nt < 4; nt++) {
            int gn = n0 + wn*32 + nt*8 + (lane & 3) * 2;
            float bn0v = 0.f, bn1v = 0.f;
            if (BIASM == 2) { bn0v = bias[gn]; bn1v = bias[gn + 1]; }
#pragma unroll
            for (int h = 0; h < 2; h++) {
                int row = m0 + wm*32 + mt*16 + (lane >> 2) + h*8;
                if (row >= M) continue;
                float x0 = acc[mt][nt][h*2 + 0];
                float x1 = acc[mt][nt][h*2 + 1];
                if (BIASM == 1) { float bm = bias[row]; x0 += bm; x1 += bm; }
                if (BIASM == 2) { x0 += bn0v; x1 += bn1v; }
                if (ACT == 1) { x0 = fmaxf(x0, 0.f); x1 = fmaxf(x1, 0.f); }
                if (ACT == 2) { x0 = gelu_f(x0); x1 = gelu_f(x1); }
                if (RES) {
                    float2 r2 = *(const float2*)&R[(long)row * N + gn];
                    x0 += r2.x; x1 += r2.y;
                }
                if (OUTF) {
                    float2 o; o.x = x0; o.y = x1;
                    *(float2*)&C[(long)row * N + gn] = o;
                }
                if (OUTS) {
                    __nv_bfloat16 h0, l0, h1, l1;
                    split_bf16(x0, h0, l0);
                    split_bf16(x1, h1, l1);
                    *(uint32_t*)&Oh[(long)row * N + gn] = pk2(h0, h1);
                    *(uint32_t*)&Ol[(long)row * N + gn] = pk2(l0, l1);
                }
            }
        }
    }
}

// ---------------- per-query offset ----------------
__global__ void off_kernel(const float* __restrict__ q4, const float* __restrict__ sb,
                           const float* __restrict__ hb, float* __restrict__ off)
{
    int n = blockIdx.x * blockDim.x + threadIdx.x;
    if (n >= Bb*Nq) return;
    float s = hb[0];
#pragma unroll 8
    for (int i = 0; i < IDim; i++) s += q4[(long)n * IDim + i] * sb[i];
    off[n] = s;
}

// ---------------- bilinear 2x upsample + offset ----------------
__global__ void upsample_kernel(const float* __restrict__ m, const float* __restrict__ off,
                                float* __restrict__ out)
{
    long idx = (long)blockIdx.x * blockDim.x + threadIdx.x;
    const long tot4 = (long)Bb * Nq * H2 * (W2 / 4);
    if (idx >= tot4) return;
    int wq4 = (int)(idx % (W2 / 4)) * 4;
    int h2 = (int)((idx / (W2 / 4)) % H2);
    long bn = idx / ((long)(W2 / 4) * H2);

    float fh = h2 * 0.5f - 0.25f;
    int h0f = (int)floorf(fh);
    float wh = fh - (float)h0f;
    int h0 = max(h0f, 0), h1 = min(h0f + 1, Hh - 1);

    const float* r0 = m + bn * (long)HW + h0 * Ww;
    const float* r1 = m + bn * (long)HW + h1 * Ww;
    float o = off[bn];

    float r[4];
#pragma unroll
    for (int j = 0; j < 4; j++) {
        int w2 = wq4 + j;
        float fw = w2 * 0.5f - 0.25f;
        int w0f = (int)floorf(fw);
        float ww = fw - (float)w0f;
        int w0 = max(w0f, 0), w1 = min(w0f + 1, Ww - 1);
        float t0 = r0[w0] * (1.f - ww) + r0[w1] * ww;
        float t1 = r1[w0] * (1.f - ww) + r1[w1] * ww;
        r[j] = t0 * (1.f - wh) + t1 * wh + o;
    }
    float4 v = make_float4(r[0], r[1], r[2], r[3]);
    *(float4*)(out + bn * (long)(H2 * W2) + (long)h2 * W2 + wq4) = v;
}

// ---------------- launcher ----------------
extern "C" void kernel_launch(void* const* d_in, const int* in_sizes, int n_in,
                              void* d_out, int out_size)
{
    const float* spat    = (const float*)d_in[0];
    const float* qf      = (const float*)d_in[1];
    const float* dw_w    = (const float*)d_in[2];
    const float* dw_b    = (const float*)d_in[3];
    const float* ln_w    = (const float*)d_in[4];
    const float* ln_b    = (const float*)d_in[5];
    const float* pw_w    = (const float*)d_in[6];
    const float* pw_b    = (const float*)d_in[7];
    const float* sproj_w = (const float*)d_in[8];
    const float* sproj_b = (const float*)d_in[9];
    const float* mlp_w1  = (const float*)d_in[10];
    const float* mlp_b1  = (const float*)d_in[11];
    const float* mlp_w2  = (const float*)d_in[12];
    const float* mlp_b2  = (const float*)d_in[13];
    const float* mlp_w3  = (const float*)d_in[14];
    const float* mlp_b3  = (const float*)d_in[15];
    const float* qproj_w = (const float*)d_in[16];
    const float* qproj_b = (const float*)d_in[17];
    const float* head_b  = (const float*)d_in[18];
    float* out = (float*)d_out;

    float *px, *pt, *pq4, *poff, *pm;
    cudaGetSymbolAddress((void**)&px,   g_x);
    cudaGetSymbolAddress((void**)&pt,   g_t);
    cudaGetSymbolAddress((void**)&pq4,  g_q4);
    cudaGetSymbolAddress((void**)&poff, g_off);
    cudaGetSymbolAddress((void**)&pm,   g_m);

    __nv_bfloat16 *pwh,*pwl,*w1h,*w1l,*w2h,*w2l,*w3h,*w3l,*qph,*qpl,*sph,*spl;
    __nv_bfloat16 *qfh,*qfl,*o1h,*o1l,*o2h,*o2l,*o3h,*o3l,*o4h,*o4l,*qqh,*qql,*bsh,*bsl,*ysh,*ysl;
    cudaGetSymbolAddress((void**)&pwh, g_pwh); cudaGetSymbolAddress((void**)&pwl, g_pwl);
    cudaGetSymbolAddress((void**)&w1h, g_w1h); cudaGetSymbolAddress((void**)&w1l, g_w1l);
    cudaGetSymbolAddress((void**)&w2h, g_w2h); cudaGetSymbolAddress((void**)&w2l, g_w2l);
    cudaGetSymbolAddress((void**)&w3h, g_w3h); cudaGetSymbolAddress((void**)&w3l, g_w3l);
    cudaGetSymbolAddress((void**)&qph, g_qph); cudaGetSymbolAddress((void**)&qpl, g_qpl);
    cudaGetSymbolAddress((void**)&sph, g_sph); cudaGetSymbolAddress((void**)&spl, g_spl);
    cudaGetSymbolAddress((void**)&qfh, g_qfh); cudaGetSymbolAddress((void**)&qfl, g_qfl);
    cudaGetSymbolAddress((void**)&o1h, g_o1h); cudaGetSymbolAddress((void**)&o1l, g_o1l);
    cudaGetSymbolAddress((void**)&o2h, g_o2h); cudaGetSymbolAddress((void**)&o2l, g_o2l);
    cudaGetSymbolAddress((void**)&o3h, g_o3h); cudaGetSymbolAddress((void**)&o3l, g_o3l);
    cudaGetSymbolAddress((void**)&o4h, g_o4h); cudaGetSymbolAddress((void**)&o4l, g_o4l);
    cudaGetSymbolAddress((void**)&qqh, g_qqh); cudaGetSymbolAddress((void**)&qql, g_qql);
    cudaGetSymbolAddress((void**)&bsh, g_bsh); cudaGetSymbolAddress((void**)&bsl, g_bsl);
    cudaGetSymbolAddress((void**)&ysh, g_ysh); cudaGetSymbolAddress((void**)&ysl, g_ysl);

    // raise smem caps (idempotent)
    cudaFuncSetAttribute(gemm_ps<1,2,false,false,true>,  cudaFuncAttributeMaxDynamicSharedMemorySize, SMEMB);
    cudaFuncSetAttribute(gemm_ps<2,1,true,true,false>,   cudaFuncAttributeMaxDynamicSharedMemorySize, SMEMB);
    cudaFuncSetAttribute(gemm_ps<2,1,true,false,true>,   cudaFuncAttributeMaxDynamicSharedMemorySize, SMEMB);
    cudaFuncSetAttribute(gemm_ps<0,2,false,false,true>,  cudaFuncAttributeMaxDynamicSharedMemorySize, SMEMB);
    cudaFuncSetAttribute(gemm_ps<0,2,false,true,true>,   cudaFuncAttributeMaxDynamicSharedMemorySize, SMEMB);
    cudaFuncSetAttribute(gemm_ps<0,0,false,false,true>,  cudaFuncAttributeMaxDynamicSharedMemorySize, SMEMB);
    cudaFuncSetAttribute(gemm_ps<0,0,false,true,false>,  cudaFuncAttributeMaxDynamicSharedMemorySize, SMEMB);

    dim3 dwBlock(80, 4);
    dim3 dwGrid(1, Hh / 4, Bb * Cc);
    dim3 tBlock(32, 8);
    const int pix = Bb * HW;
    const int Mq = Bb * Nq;

    // #1..#3: dw0, stats0(LN+split), pw weight split
    dw_kernel<<<dwGrid, dwBlock>>>(spat, dw_w, dw_b, pt);
    stats_kernel<<<(pix + 255)/256, 256>>>(pt, ln_w, ln_b, bsh, bsl);
    split_k<<<(2*Cc*Cc/4 + 255)/256, 256>>>(pw_w, pwh, pwl, 2*Cc*Cc/4);

    // #4: pw GEMM block0 (profiling target): C[c][pix] f32 + resid
    gemm_ps<2, 1, true, true, false><<<dim3(HW/64, 2, Bb), 256, SMEMB>>>(
        pwh, pwl, bsh, bsl, pw_b, spat, px, nullptr, nullptr,
        Cc, HW, Cc, 0, (long)CHW, (long)CHW);

    // spatial block 1: dw1 -> stats1 -> pw1 (emit y split planes only)
    dw_kernel<<<dwGrid, dwBlock>>>(px, dw_w + Cc*9, dw_b + Cc, pt);
    stats_kernel<<<(pix + 255)/256, 256>>>(pt, ln_w + Cc, ln_b + Cc, bsh, bsl);
    gemm_ps<2, 1, true, false, true><<<dim3(HW/64, 2, Bb), 256, SMEMB>>>(
        pwh + Cc*Cc, pwl + Cc*Cc, bsh, bsl, pw_b + Cc, px, nullptr, ysh, ysl,
        Cc, HW, Cc, 0, (long)CHW, (long)CHW);

    // query-side weight/input splits
    split_k<<<(Mq*Cc/4 + 255)/256, 256>>>(qf, qfh, qfl, Mq*Cc/4);
    splitT_k<<<dim3(Cc/32, HID/32, 1), tBlock>>>(mlp_w1, w1h, w1l, HID, Cc);     // [256][512]
    splitT_k<<<dim3(HID/32, HID/32, 1), tBlock>>>(mlp_w2, w2h, w2l, HID, HID);   // [512][512]
    splitT_k<<<dim3(HID/32, Cc/32, 1), tBlock>>>(mlp_w3, w3h, w3l, Cc, HID);     // [512][256]
    splitT_k<<<dim3(Cc/32, IDim/32, 1), tBlock>>>(qproj_w, qph, qpl, IDim, Cc);  // [256][128]
    split_k<<<(IDim*Cc/4 + 255)/256, 256>>>(sproj_w, sph, spl, IDim*Cc/4);       // [128][256]

    // query MLP chain (M = 1200)
    gemm_ps<1, 2, false, false, true><<<dim3(HID/64, 10, 1), 256, SMEMB>>>(
        qfh, qfl, w1h, w1l, mlp_b1, nullptr, nullptr, o1h, o1l,
        Mq, HID, Cc, 0, 0, 0);
    gemm_ps<1, 2, false, false, true><<<dim3(HID/64, 10, 1), 256, SMEMB>>>(
        o1h, o1l, w2h, w2l, mlp_b2, nullptr, nullptr, o2h, o2l,
        Mq, HID, HID, 0, 0, 0);
    gemm_ps<0, 2, false, false, true><<<dim3(Cc/64, 10, 1), 256, SMEMB>>>(
        o2h, o2l, w3h, w3l, mlp_b3, nullptr, nullptr, o3h, o3l,
        Mq, Cc, HID, 0, 0, 0);
    gemm_ps<0, 2, false, true, true><<<dim3(IDim/64, 10, 1), 256, SMEMB>>>(
        o3h, o3l, qph, qpl, qproj_b, nullptr, pq4, o4h, o4l,
        Mq, IDim, Cc, 0, 0, 0);
    gemm_ps<0, 0, false, false, true><<<dim3(Cc/64, 10, 1), 256, SMEMB>>>(
        o4h, o4l, sph, spl, nullptr, nullptr, nullptr, qqh, qql,
        Mq, Cc, IDim, 0, 0, 0);
    off_kernel<<<(Mq + 255)/256, 256>>>(pq4, sproj_b, head_b, poff);

    // mask GEMM at 80x80: m[b,n,p] = sum_c qq[b,n,c] * y[b,c,p]
    gemm_ps<0, 0, false, true, false><<<dim3(HW/64, 3, Bb), 256, SMEMB>>>(
        qqh, qql, ysh, ysl, nullptr, nullptr, pm, nullptr, nullptr,
        Nq, HW, Cc, (long)Nq*Cc, (long)CHW, (long)Nq*HW);

    // bilinear 2x upsample + per-(b,n) offset
    const long tot4 = (long)Bb * Nq * H2 * (W2 / 4);
    upsample_kernel<<<(unsigned)((tot4 + 255)/256), 256>>>(pm, poff, out);
}

// round 11
// speedup vs baseline: 1.2717x; 1.0026x over previous
#include <cuda_runtime.h>
#include <cuda_bf16.h>
#include <math.h>
#include <stdint.h>
#include <string.h>

// ---------------- problem constants ----------------
#define Bb 4
#define Cc 256
#define Hh 80
#define Ww 80
#define Nq 300
#define IDim 128
#define HID 512
#define H2 160
#define W2 160
#define HW (Hh*Ww)
#define CHW (Cc*HW)

// ---------------- GEMM tile geometry ----------------
// BM=128, BN=64, BK=32, 3-stage cp.async pipeline.
#define RS 40
#define RSB 72
#define STG_A_H 0
#define STG_A_L 10240
#define STG_B_H 20480
#define STG_B_L 25088
#define STG_SZ 29696
#define SMEMB (3*STG_SZ)            // 89088

// ---------------- device scratch (f32) ----------------
__device__ float g_x[Bb*CHW];
__device__ float g_t[Bb*CHW];
__device__ float g_q4[Bb*Nq*IDim];
__device__ float g_off[Bb*Nq];
__device__ float g_m[Bb*Nq*HW];

// ---------------- device scratch (bf16 hi/lo planes) ----------------
__device__ __nv_bfloat16 g_pwh[2*Cc*Cc],  g_pwl[2*Cc*Cc];
__device__ __nv_bfloat16 g_w1h[Cc*HID],   g_w1l[Cc*HID];
__device__ __nv_bfloat16 g_w2h[HID*HID],  g_w2l[HID*HID];
__device__ __nv_bfloat16 g_w3h[HID*Cc],   g_w3l[HID*Cc];
__device__ __nv_bfloat16 g_qph[Cc*IDim],  g_qpl[Cc*IDim];
__device__ __nv_bfloat16 g_sph[IDim*Cc],  g_spl[IDim*Cc];
__device__ __nv_bfloat16 g_qfh[Bb*Nq*Cc], g_qfl[Bb*Nq*Cc];
__device__ __nv_bfloat16 g_o1h[Bb*Nq*HID],g_o1l[Bb*Nq*HID];
__device__ __nv_bfloat16 g_o2h[Bb*Nq*HID],g_o2l[Bb*Nq*HID];
__device__ __nv_bfloat16 g_o3h[Bb*Nq*Cc], g_o3l[Bb*Nq*Cc];
__device__ __nv_bfloat16 g_o4h[Bb*Nq*IDim],g_o4l[Bb*Nq*IDim];
__device__ __nv_bfloat16 g_qqh[Bb*Nq*Cc], g_qql[Bb*Nq*Cc];
__device__ __nv_bfloat16 g_bsh[Bb*CHW],   g_bsl[Bb*CHW];
__device__ __nv_bfloat16 g_ysh[Bb*CHW],   g_ysl[Bb*CHW];

__device__ __forceinline__ float gelu_f(float x) {
    return 0.5f * x * (1.0f + erff(x * 0.70710678118654752f));
}
__device__ __forceinline__ uint32_t su32(const void* p) {
    return (uint32_t)__cvta_generic_to_shared(p);
}
__device__ __forceinline__ void ldsm4(uint32_t* r, uint32_t addr) {
    asm volatile("ldmatrix.sync.aligned.m8n8.x4.shared.b16 {%0,%1,%2,%3}, [%4];"
        : "=r"(r[0]), "=r"(r[1]), "=r"(r[2]), "=r"(r[3]) : "r"(addr));
}
__device__ __forceinline__ void ldsm4t(uint32_t* r, uint32_t addr) {
    asm volatile("ldmatrix.sync.aligned.m8n8.x4.trans.shared.b16 {%0,%1,%2,%3}, [%4];"
        : "=r"(r[0]), "=r"(r[1]), "=r"(r[2]), "=r"(r[3]) : "r"(addr));
}
__device__ __forceinline__ void mma16816(float* d, const uint32_t* a, const uint32_t* b) {
    asm volatile("mma.sync.aligned.m16n8k16.row.col.f32.bf16.bf16.f32 "
        "{%0,%1,%2,%3}, {%4,%5,%6,%7}, {%8,%9}, {%0,%1,%2,%3};"
        : "+f"(d[0]), "+f"(d[1]), "+f"(d[2]), "+f"(d[3])
        : "r"(a[0]), "r"(a[1]), "r"(a[2]), "r"(a[3]), "r"(b[0]), "r"(b[1]));
}
__device__ __forceinline__ void split_bf16(float x, __nv_bfloat16& hi, __nv_bfloat16& lo) {
    hi = __float2bfloat16(x);
    lo = __float2bfloat16(x - __bfloat162float(hi));
}
__device__ __forceinline__ uint32_t pk2(__nv_bfloat16 a, __nv_bfloat16 b) {
    __nv_bfloat162 t(a, b);
    uint32_t u;
    memcpy(&u, &t, 4);
    return u;
}
__device__ __forceinline__ void cpa16(uint32_t d, const void* s, int bytes) {
    asm volatile("cp.async.cg.shared.global [%0], [%1], 16, %2;"
        :: "r"(d), "l"(s), "r"(bytes));
}
#define CP_COMMIT asm volatile("cp.async.commit_group;")
#define CP_WAIT1  asm volatile("cp.async.wait_group 1;")

// ---------------- depthwise 3x3 conv (SAME) + bias ----------------
__global__ void dw_kernel(const float* __restrict__ x, const float* __restrict__ w,
                          const float* __restrict__ bia, float* __restrict__ out)
{
    int wq = threadIdx.x;
    int hq = blockIdx.y * 4 + threadIdx.y;
    int plane = blockIdx.z;
    int c = plane & (Cc - 1);
    const float* xp = x + (long)plane * HW;
    const float* wp = w + c * 9;
    float w00 = wp[0], w01 = wp[1], w02 = wp[2];
    float w10 = wp[3], w11 = wp[4], w12 = wp[5];
    float w20 = wp[6], w21 = wp[7], w22 = wp[8];
    float acc = bia[c];

    const float* r0 = xp + (hq - 1) * Ww;
    const float* r1 = xp + hq * Ww;
    const float* r2 = xp + (hq + 1) * Ww;
    bool ht = hq > 0, hb = hq < Hh - 1;
    bool wl = wq > 0, wr = wq < Ww - 1;

    if (ht) {
        if (wl) acc += w00 * r0[wq - 1];
        acc += w01 * r0[wq];
        if (wr) acc += w02 * r0[wq + 1];
    }
    {
        if (wl) acc += w10 * r1[wq - 1];
        acc += w11 * r1[wq];
        if (wr) acc += w12 * r1[wq + 1];
    }
    if (hb) {
        if (wl) acc += w20 * r2[wq - 1];
        acc += w21 * r2[wq];
        if (wr) acc += w22 * r2[wq + 1];
    }
    out[(long)plane * HW + hq * Ww + wq] = acc;
}

// ---------------- LN stats + apply + split, [c][pix] planes ----------------
__global__ void stats_kernel(const float* __restrict__ t,
                             const float* __restrict__ lw, const float* __restrict__ lb,
                             __nv_bfloat16* __restrict__ oh, __nv_bfloat16* __restrict__ ol)
{
    int p = blockIdx.x * blockDim.x + threadIdx.x;
    if (p >= Bb*HW) return;
    int bb = p / HW;
    int pix = p - bb * HW;
    const float* base = t + (long)bb * CHW + pix;
    float s = 0.f, s2 = 0.f;
#pragma unroll 8
    for (int c = 0; c < Cc; c++) {
        float v = base[(long)c * HW];
        s += v; s2 += v * v;
    }
    float m = s * (1.0f / Cc);
    float var = s2 * (1.0f / Cc) - m * m;
    float inv = rsqrtf(var + 1e-6f);

    __nv_bfloat16* po = oh + (long)bb * CHW + pix;
    __nv_bfloat16* pl = ol + (long)bb * CHW + pix;
#pragma unroll 4
    for (int c = 0; c < Cc; c++) {
        float v = (base[(long)c * HW] - m) * inv * lw[c] + lb[c];
        __nv_bfloat16 h, l;
        split_bf16(v, h, l);
        po[(long)c * HW] = h;
        pl[(long)c * HW] = l;
    }
}

// ---------------- elementwise split f32 -> bf16 hi/lo ----------------
__global__ void split_k(const float* __restrict__ src,
                        __nv_bfloat16* __restrict__ hi, __nv_bfloat16* __restrict__ lo,
                        int n4)
{
    int i = blockIdx.x * blockDim.x + threadIdx.x;
    if (i >= n4) return;
    float4 v = ((const float4*)src)[i];
    __nv_bfloat16 h0,l0,h1,l1,h2,l2,h3,l3;
    split_bf16(v.x,h0,l0); split_bf16(v.y,h1,l1);
    split_bf16(v.z,h2,l2); split_bf16(v.w,h3,l3);
    ((uint32_t*)hi)[i*2]   = pk2(h0,h1);
    ((uint32_t*)hi)[i*2+1] = pk2(h2,h3);
    ((uint32_t*)lo)[i*2]   = pk2(l0,l1);
    ((uint32_t*)lo)[i*2+1] = pk2(l2,l3);
}

// ---------------- transpose + split ----------------
__global__ void splitT_k(const float* __restrict__ X,
                         __nv_bfloat16* __restrict__ Oh, __nv_bfloat16* __restrict__ Ol,
                         int Krows, int Ncols)
{
    int z = blockIdx.z;
    long zoff = (long)z * Krows * Ncols;
    X += zoff; Oh += zoff; Ol += zoff;

    __shared__ float ts[32][33];
    int n0 = blockIdx.x * 32, k0 = blockIdx.y * 32;
    int tx = threadIdx.x, ty = threadIdx.y;

#pragma unroll
    for (int j = 0; j < 4; j++)
        ts[ty + j*8][tx] = X[(long)(k0 + ty + j*8) * Ncols + n0 + tx];
    __syncthreads();

#pragma unroll
    for (int j = 0; j < 4; j++) {
        int n = n0 + ty + j*8;
        int k = k0 + tx;
        float v = ts[tx][ty + j*8];
        __nv_bfloat16 h, l;
        split_bf16(v, h, l);
        Oh[(long)n * Krows + k] = h;
        Ol[(long)n * Krows + k] = l;
    }
}

// ---------------- bf16 tensor-core GEMM, pre-split streaming ----------------
// Pass-major MMA ordering: 8 independent accumulators between reuses.
template<int ACT, int BIASM, bool RES, bool OUTF, bool OUTS>
__global__ void __launch_bounds__(256, 2)
gemm_ps(const __nv_bfloat16* __restrict__ Ah_g, const __nv_bfloat16* __restrict__ Al_g,
        const __nv_bfloat16* __restrict__ Bh_g, const __nv_bfloat16* __restrict__ Bl_g,
        const float* __restrict__ bias, const float* __restrict__ resid,
        float* __restrict__ C, __nv_bfloat16* __restrict__ Oh, __nv_bfloat16* __restrict__ Ol,
        int M, int N, int K, long sA, long sB, long sC)
{
    extern __shared__ __align__(16) char dsm[];
    uint32_t sb = su32(dsm);

    int z = blockIdx.z;
    Ah_g += z * sA; Al_g += z * sA;
    Bh_g += z * sB; Bl_g += z * sB;
    if (OUTF) C += z * sC;
    if (OUTS) { Oh += z * sC; Ol += z * sC; }
    const float* R = RES ? (resid + z * sC) : nullptr;

    int m0 = blockIdx.y * 128;
    int n0 = blockIdx.x * 64;
    int tid = threadIdx.x;
    int warp = tid >> 5;
    int lane = tid & 31;
    int wm = warp & 3;
    int wn = warp >> 2;

    int a_r = tid >> 1;
    int a_c = (tid & 1) * 2;
    int b_r = tid >> 3;
    int b_c = tid & 7;

    const int KT = K >> 5;

    auto loadStage = [&](int st, int kb) {
        uint32_t abase = sb + st * STG_SZ;
        bool mok = (m0 + a_r) < M;
        int ab = mok ? 16 : 0;
        const __nv_bfloat16* sh = Ah_g + (long)(m0 + a_r) * K + kb;
        const __nv_bfloat16* sl = Al_g + (long)(m0 + a_r) * K + kb;
        uint32_t dA = abase + a_r * 80 + a_c * 16;
#pragma unroll
        for (int j = 0; j < 2; j++) {
            cpa16(dA + STG_A_H + j * 16, sh + (a_c + j) * 8, ab);
            cpa16(dA + STG_A_L + j * 16, sl + (a_c + j) * 8, ab);
        }
        const __nv_bfloat16* bh = Bh_g + (long)(kb + b_r) * N + n0 + b_c * 8;
        const __nv_bfloat16* bl = Bl_g + (long)(kb + b_r) * N + n0 + b_c * 8;
        uint32_t dB = abase + b_r * 144 + b_c * 16;
        cpa16(dB + STG_B_H, bh, 16);
        cpa16(dB + STG_B_L, bl, 16);
    };

    loadStage(0, 0);
    CP_COMMIT;
    if (KT > 1) loadStage(1, 32);
    CP_COMMIT;

    float acc[2][4][4];
#pragma unroll
    for (int i = 0; i < 2; i++)
#pragma unroll
        for (int j = 0; j < 4; j++)
#pragma unroll
            for (int q = 0; q < 4; q++) acc[i][j][q] = 0.f;

    int a_mrow = lane & 15;
    int a_kh = (lane >> 4) * 8;
    int bg = lane >> 3;
    int b_kr = (bg & 1) * 8 + (lane & 7);
    int b_nc = (bg >> 1) * 8;

    int st = 0;
    for (int kt = 0; kt < KT; kt++) {
        CP_WAIT1;
        __syncthreads();
        if (kt + 2 < KT) loadStage((st + 2 >= 3) ? st - 1 : st + 2, (kt + 2) << 5);
        CP_COMMIT;

        uint32_t base = sb + st * STG_SZ;
#pragma unroll
        for (int half = 0; half < 2; half++) {
            int kc = half * 16;
            // ---- load all fragments for this k16 up-front ----
            uint32_t afr[2][2][4];   // [split][mt]
#pragma unroll
            for (int s = 0; s < 2; s++) {
                uint32_t ap = base + (s ? STG_A_L : STG_A_H);
#pragma unroll
                for (int mt = 0; mt < 2; mt++)
                    ldsm4(afr[s][mt], ap + ((wm*32 + mt*16 + a_mrow) * RS + kc + a_kh) * 2);
            }
            uint32_t bfr[2][2][4];   // [p][split]
#pragma unroll
            for (int p = 0; p < 2; p++) {
                uint32_t boff = ((kc + b_kr) * RSB + wn*32 + p*16 + b_nc) * 2;
                ldsm4t(bfr[p][0], base + STG_B_H + boff);
                ldsm4t(bfr[p][1], base + STG_B_L + boff);
            }
            // ---- pass-major: 8 independent MMAs per pass ----
#pragma unroll
            for (int p = 0; p < 2; p++)     // pass hi*hi
#pragma unroll
                for (int mt = 0; mt < 2; mt++) {
                    mma16816(acc[mt][2*p],   afr[0][mt], bfr[p][0]);
                    mma16816(acc[mt][2*p+1], afr[0][mt], bfr[p][0] + 2);
                }
#pragma unroll
            for (int p = 0; p < 2; p++)     // pass hi*lo
#pragma unroll
                for (int mt = 0; mt < 2; mt++) {
                    mma16816(acc[mt][2*p],   afr[0][mt], bfr[p][1]);
                    mma16816(acc[mt][2*p+1], afr[0][mt], bfr[p][1] + 2);
                }
#pragma unroll
            for (int p = 0; p < 2; p++)     // pass lo*hi
#pragma unroll
                for (int mt = 0; mt < 2; mt++) {
                    mma16816(acc[mt][2*p],   afr[1][mt], bfr[p][0]);
                    mma16816(acc[mt][2*p+1], afr[1][mt], bfr[p][0] + 2);
                }
        }
        st++;
        if (st == 3) st = 0;
    }

    // ---- epilogue ----
#pragma unroll
    for (int mt = 0; mt < 2; mt++) {
#pragma unroll
        for (int nt = 0; nt < 4; nt++) {
            int gn = n0 + wn*32 + nt*8 + (lane & 3) * 2;
            float bn0v = 0.f, bn1v = 0.f;
            if (BIASM == 2) { bn0v = bias[gn]; bn1v = bias[gn + 1]; }
#pragma unroll
            for (int h = 0; h < 2; h++) {
                int row = m0 + wm*32 + mt*16 + (lane >> 2) + h*8;
                if (row >= M) continue;
                float x0 = acc[mt][nt][h*2 + 0];
                float x1 = acc[mt][nt][h*2 + 1];
                if (BIASM == 1) { float bm = bias[row]; x0 += bm; x1 += bm; }
                if (BIASM == 2) { x0 += bn0v; x1 += bn1v; }
                if (ACT == 1) { x0 = fmaxf(x0, 0.f); x1 = fmaxf(x1, 0.f); }
                if (ACT == 2) { x0 = gelu_f(x0); x1 = gelu_f(x1); }
                if (RES) {
                    float2 r2 = *(const float2*)&R[(long)row * N + gn];
                    x0 += r2.x; x1 += r2.y;
                }
                if (OUTF) {
                    float2 o; o.x = x0; o.y = x1;
                    *(float2*)&C[(long)row * N + gn] = o;
                }
                if (OUTS) {
                    __nv_bfloat16 h0, l0, h1, l1;
                    split_bf16(x0, h0, l0);
                    split_bf16(x1, h1, l1);
                    *(uint32_t*)&Oh[(long)row * N + gn] = pk2(h0, h1);
                    *(uint32_t*)&Ol[(long)row * N + gn] = pk2(l0, l1);
                }
            }
        }
    }
}

// ---------------- per-query offset ----------------
__global__ void off_kernel(const float* __restrict__ q4, const float* __restrict__ sb,
                           const float* __restrict__ hb, float* __restrict__ off)
{
    int n = blockIdx.x * blockDim.x + threadIdx.x;
    if (n >= Bb*Nq) return;
    float s = hb[0];
#pragma unroll 8
    for (int i = 0; i < IDim; i++) s += q4[(long)n * IDim + i] * sb[i];
    off[n] = s;
}

// ---------------- bilinear 2x upsample + offset ----------------
__global__ void upsample_kernel(const float* __restrict__ m, const float* __restrict__ off,
                                float* __restrict__ out)
{
    long idx = (long)blockIdx.x * blockDim.x + threadIdx.x;
    const long tot4 = (long)Bb * Nq * H2 * (W2 / 4);
    if (idx >= tot4) return;
    int wq4 = (int)(idx % (W2 / 4)) * 4;
    int h2 = (int)((idx / (W2 / 4)) % H2);
    long bn = idx / ((long)(W2 / 4) * H2);

    float fh = h2 * 0.5f - 0.25f;
    int h0f = (int)floorf(fh);
    float wh = fh - (float)h0f;
    int h0 = max(h0f, 0), h1 = min(h0f + 1, Hh - 1);

    const float* r0 = m + bn * (long)HW + h0 * Ww;
    const float* r1 = m + bn * (long)HW + h1 * Ww;
    float o = off[bn];

    float r[4];
#pragma unroll
    for (int j = 0; j < 4; j++) {
        int w2 = wq4 + j;
        float fw = w2 * 0.5f - 0.25f;
        int w0f = (int)floorf(fw);
        float ww = fw - (float)w0f;
        int w0 = max(w0f, 0), w1 = min(w0f + 1, Ww - 1);
        float t0 = r0[w0] * (1.f - ww) + r0[w1] * ww;
        float t1 = r1[w0] * (1.f - ww) + r1[w1] * ww;
        r[j] = t0 * (1.f - wh) + t1 * wh + o;
    }
    float4 v = make_float4(r[0], r[1], r[2], r[3]);
    *(float4*)(out + bn * (long)(H2 * W2) + (long)h2 * W2 + wq4) = v;
}

// ---------------- launcher ----------------
extern "C" void kernel_launch(void* const* d_in, const int* in_sizes, int n_in,
                              void* d_out, int out_size)
{
    const float* spat    = (const float*)d_in[0];
    const float* qf      = (const float*)d_in[1];
    const float* dw_w    = (const float*)d_in[2];
    const float* dw_b    = (const float*)d_in[3];
    const float* ln_w    = (const float*)d_in[4];
    const float* ln_b    = (const float*)d_in[5];
    const float* pw_w    = (const float*)d_in[6];
    const float* pw_b    = (const float*)d_in[7];
    const float* sproj_w = (const float*)d_in[8];
    const float* sproj_b = (const float*)d_in[9];
    const float* mlp_w1  = (const float*)d_in[10];
    const float* mlp_b1  = (const float*)d_in[11];
    const float* mlp_w2  = (const float*)d_in[12];
    const float* mlp_b2  = (const float*)d_in[13];
    const float* mlp_w3  = (const float*)d_in[14];
    const float* mlp_b3  = (const float*)d_in[15];
    const float* qproj_w = (const float*)d_in[16];
    const float* qproj_b = (const float*)d_in[17];
    const float* head_b  = (const float*)d_in[18];
    float* out = (float*)d_out;

    float *px, *pt, *pq4, *poff, *pm;
    cudaGetSymbolAddress((void**)&px,   g_x);
    cudaGetSymbolAddress((void**)&pt,   g_t);
    cudaGetSymbolAddress((void**)&pq4,  g_q4);
    cudaGetSymbolAddress((void**)&poff, g_off);
    cudaGetSymbolAddress((void**)&pm,   g_m);

    __nv_bfloat16 *pwh,*pwl,*w1h,*w1l,*w2h,*w2l,*w3h,*w3l,*qph,*qpl,*sph,*spl;
    __nv_bfloat16 *qfh,*qfl,*o1h,*o1l,*o2h,*o2l,*o3h,*o3l,*o4h,*o4l,*qqh,*qql,*bsh,*bsl,*ysh,*ysl;
    cudaGetSymbolAddress((void**)&pwh, g_pwh); cudaGetSymbolAddress((void**)&pwl, g_pwl);
    cudaGetSymbolAddress((void**)&w1h, g_w1h); cudaGetSymbolAddress((void**)&w1l, g_w1l);
    cudaGetSymbolAddress((void**)&w2h, g_w2h); cudaGetSymbolAddress((void**)&w2l, g_w2l);
    cudaGetSymbolAddress((void**)&w3h, g_w3h); cudaGetSymbolAddress((void**)&w3l, g_w3l);
    cudaGetSymbolAddress((void**)&qph, g_qph); cudaGetSymbolAddress((void**)&qpl, g_qpl);
    cudaGetSymbolAddress((void**)&sph, g_sph); cudaGetSymbolAddress((void**)&spl, g_spl);
    cudaGetSymbolAddress((void**)&qfh, g_qfh); cudaGetSymbolAddress((void**)&qfl, g_qfl);
    cudaGetSymbolAddress((void**)&o1h, g_o1h); cudaGetSymbolAddress((void**)&o1l, g_o1l);
    cudaGetSymbolAddress((void**)&o2h, g_o2h); cudaGetSymbolAddress((void**)&o2l, g_o2l);
    cudaGetSymbolAddress((void**)&o3h, g_o3h); cudaGetSymbolAddress((void**)&o3l, g_o3l);
    cudaGetSymbolAddress((void**)&o4h, g_o4h); cudaGetSymbolAddress((void**)&o4l, g_o4l);
    cudaGetSymbolAddress((void**)&qqh, g_qqh); cudaGetSymbolAddress((void**)&qql, g_qql);
    cudaGetSymbolAddress((void**)&bsh, g_bsh); cudaGetSymbolAddress((void**)&bsl, g_bsl);
    cudaGetSymbolAddress((void**)&ysh, g_ysh); cudaGetSymbolAddress((void**)&ysl, g_ysl);

    cudaFuncSetAttribute(gemm_ps<1,2,false,false,true>,  cudaFuncAttributeMaxDynamicSharedMemorySize, SMEMB);
    cudaFuncSetAttribute(gemm_ps<2,1,true,true,false>,   cudaFuncAttributeMaxDynamicSharedMemorySize, SMEMB);
    cudaFuncSetAttribute(gemm_ps<2,1,true,false,true>,   cudaFuncAttributeMaxDynamicSharedMemorySize, SMEMB);
    cudaFuncSetAttribute(gemm_ps<0,2,false,false,true>,  cudaFuncAttributeMaxDynamicSharedMemorySize, SMEMB);
    cudaFuncSetAttribute(gemm_ps<0,2,false,true,true>,   cudaFuncAttributeMaxDynamicSharedMemorySize, SMEMB);
    cudaFuncSetAttribute(gemm_ps<0,0,false,false,true>,  cudaFuncAttributeMaxDynamicSharedMemorySize, SMEMB);
    cudaFuncSetAttribute(gemm_ps<0,0,false,true,false>,  cudaFuncAttributeMaxDynamicSharedMemorySize, SMEMB);

    dim3 dwBlock(80, 4);
    dim3 dwGrid(1, Hh / 4, Bb * Cc);
    dim3 tBlock(32, 8);
    const int pix = Bb * HW;
    const int Mq = Bb * Nq;

    dw_kernel<<<dwGrid, dwBlock>>>(spat, dw_w, dw_b, pt);
    stats_kernel<<<(pix + 255)/256, 256>>>(pt, ln_w, ln_b, bsh, bsl);
    split_k<<<(2*Cc*Cc/4 + 255)/256, 256>>>(pw_w, pwh, pwl, 2*Cc*Cc/4);

    // pw GEMM block0 (profiling target)
    gemm_ps<2, 1, true, true, false><<<dim3(HW/64, 2, Bb), 256, SMEMB>>>(
        pwh, pwl, bsh, bsl, pw_b, spat, px, nullptr, nullptr,
        Cc, HW, Cc, 0, (long)CHW, (long)CHW);

    dw_kernel<<<dwGrid, dwBlock>>>(px, dw_w + Cc*9, dw_b + Cc, pt);
    stats_kernel<<<(pix + 255)/256, 256>>>(pt, ln_w + Cc, ln_b + Cc, bsh, bsl);
    gemm_ps<2, 1, true, false, true><<<dim3(HW/64, 2, Bb), 256, SMEMB>>>(
        pwh + Cc*Cc, pwl + Cc*Cc, bsh, bsl, pw_b + Cc, px, nullptr, ysh, ysl,
        Cc, HW, Cc, 0, (long)CHW, (long)CHW);

    split_k<<<(Mq*Cc/4 + 255)/256, 256>>>(qf, qfh, qfl, Mq*Cc/4);
    splitT_k<<<dim3(Cc/32, HID/32, 1), tBlock>>>(mlp_w1, w1h, w1l, HID, Cc);
    splitT_k<<<dim3(HID/32, HID/32, 1), tBlock>>>(mlp_w2, w2h, w2l, HID, HID);
    splitT_k<<<dim3(HID/32, Cc/32, 1), tBlock>>>(mlp_w3, w3h, w3l, Cc, HID);
    splitT_k<<<dim3(Cc/32, IDim/32, 1), tBlock>>>(qproj_w, qph, qpl, IDim, Cc);
    split_k<<<(IDim*Cc/4 + 255)/256, 256>>>(sproj_w, sph, spl, IDim*Cc/4);

    gemm_ps<1, 2, false, false, true><<<dim3(HID/64, 10, 1), 256, SMEMB>>>(
        qfh, qfl, w1h, w1l, mlp_b1, nullptr, nullptr, o1h, o1l,
        Mq, HID, Cc, 0, 0, 0);
    gemm_ps<1, 2, false, false, true><<<dim3(HID/64, 10, 1), 256, SMEMB>>>(
        o1h, o1l, w2h, w2l, mlp_b2, nullptr, nullptr, o2h, o2l,
        Mq, HID, HID, 0, 0, 0);
    gemm_ps<0, 2, false, false, true><<<dim3(Cc/64, 10, 1), 256, SMEMB>>>(
        o2h, o2l, w3h, w3l, mlp_b3, nullptr, nullptr, o3h, o3l,
        Mq, Cc, HID, 0, 0, 0);
    gemm_ps<0, 2, false, true, true><<<dim3(IDim/64, 10, 1), 256, SMEMB>>>(
        o3h, o3l, qph, qpl, qproj_b, nullptr, pq4, o4h, o4l,
        Mq, IDim, Cc, 0, 0, 0);
    gemm_ps<0, 0, false, false, true><<<dim3(Cc/64, 10, 1), 256, SMEMB>>>(
        o4h, o4l, sph, spl, nullptr, nullptr, nullptr, qqh, qql,
        Mq, Cc, IDim, 0, 0, 0);
    off_kernel<<<(Mq + 255)/256, 256>>>(pq4, sproj_b, head_b, poff);

    gemm_ps<0, 0, false, true, false><<<dim3(HW/64, 3, Bb), 256, SMEMB>>>(
        qqh, qql, ysh, ysl, nullptr, nullptr, pm, nullptr, nullptr,
        Nq, HW, Cc, (long)Nq*Cc, (long)CHW, (long)Nq*HW);

    const long tot4 = (long)Bb * Nq * H2 * (W2 / 4);
    upsample_kernel<<<(unsigned)((tot4 + 255)/256), 256>>>(pm, poff, out);
}

// round 12
// speedup vs baseline: 1.5392x; 1.2103x over previous
#include <cuda_runtime.h>
#include <cuda_bf16.h>
#include <math.h>
#include <stdint.h>
#include <string.h>

// ---------------- problem constants ----------------
#define Bb 4
#define Cc 256
#define Hh 80
#define Ww 80
#define Nq 300
#define IDim 128
#define HID 512
#define H2 160
#define W2 160
#define HW (Hh*Ww)
#define CHW (Cc*HW)

// ---------------- GEMM tile geometry ----------------
#define RS 40
#define RSB 72
#define STG_A_H 0
#define STG_A_L 10240
#define STG_B_H 20480
#define STG_B_L 25088
#define STG_SZ 29696
#define SMEMB (3*STG_SZ)

// ---------------- device scratch (f32) ----------------
__device__ float g_x[Bb*CHW];
__device__ float g_t[Bb*CHW];
__device__ float g_q4[Bb*Nq*IDim];
__device__ float g_off[Bb*Nq];
__device__ float g_m[Bb*Nq*HW];

// ---------------- device scratch (bf16 hi/lo planes) ----------------
__device__ __nv_bfloat16 g_pwh[2*Cc*Cc],  g_pwl[2*Cc*Cc];
__device__ __nv_bfloat16 g_w1h[Cc*HID],   g_w1l[Cc*HID];
__device__ __nv_bfloat16 g_w2h[HID*HID],  g_w2l[HID*HID];
__device__ __nv_bfloat16 g_w3h[HID*Cc],   g_w3l[HID*Cc];
__device__ __nv_bfloat16 g_qph[Cc*IDim],  g_qpl[Cc*IDim];
__device__ __nv_bfloat16 g_sph[IDim*Cc],  g_spl[IDim*Cc];
__device__ __nv_bfloat16 g_qfh[Bb*Nq*Cc], g_qfl[Bb*Nq*Cc];
__device__ __nv_bfloat16 g_o1h[Bb*Nq*HID],g_o1l[Bb*Nq*HID];
__device__ __nv_bfloat16 g_o2h[Bb*Nq*HID],g_o2l[Bb*Nq*HID];
__device__ __nv_bfloat16 g_o3h[Bb*Nq*Cc], g_o3l[Bb*Nq*Cc];
__device__ __nv_bfloat16 g_o4h[Bb*Nq*IDim],g_o4l[Bb*Nq*IDim];
__device__ __nv_bfloat16 g_qqh[Bb*Nq*Cc], g_qql[Bb*Nq*Cc];
__device__ __nv_bfloat16 g_bsh[Bb*CHW],   g_bsl[Bb*CHW];
__device__ __nv_bfloat16 g_ysh[Bb*CHW],   g_ysl[Bb*CHW];

__device__ __forceinline__ float gelu_f(float x) {
    return 0.5f * x * (1.0f + erff(x * 0.70710678118654752f));
}
__device__ __forceinline__ uint32_t su32(const void* p) {
    return (uint32_t)__cvta_generic_to_shared(p);
}
__device__ __forceinline__ void ldsm4(uint32_t* r, uint32_t addr) {
    asm volatile("ldmatrix.sync.aligned.m8n8.x4.shared.b16 {%0,%1,%2,%3}, [%4];"
        : "=r"(r[0]), "=r"(r[1]), "=r"(r[2]), "=r"(r[3]) : "r"(addr));
}
__device__ __forceinline__ void ldsm4t(uint32_t* r, uint32_t addr) {
    asm volatile("ldmatrix.sync.aligned.m8n8.x4.trans.shared.b16 {%0,%1,%2,%3}, [%4];"
        : "=r"(r[0]), "=r"(r[1]), "=r"(r[2]), "=r"(r[3]) : "r"(addr));
}
__device__ __forceinline__ void mma16816(float* d, const uint32_t* a, const uint32_t* b) {
    asm volatile("mma.sync.aligned.m16n8k16.row.col.f32.bf16.bf16.f32 "
        "{%0,%1,%2,%3}, {%4,%5,%6,%7}, {%8,%9}, {%0,%1,%2,%3};"
        : "+f"(d[0]), "+f"(d[1]), "+f"(d[2]), "+f"(d[3])
        : "r"(a[0]), "r"(a[1]), "r"(a[2]), "r"(a[3]), "r"(b[0]), "r"(b[1]));
}
__device__ __forceinline__ void split_bf16(float x, __nv_bfloat16& hi, __nv_bfloat16& lo) {
    hi = __float2bfloat16(x);
    lo = __float2bfloat16(x - __bfloat162float(hi));
}
__device__ __forceinline__ uint32_t pk2(__nv_bfloat16 a, __nv_bfloat16 b) {
    __nv_bfloat162 t(a, b);
    uint32_t u;
    memcpy(&u, &t, 4);
    return u;
}
__device__ __forceinline__ void cpa16(uint32_t d, const void* s, int bytes) {
    asm volatile("cp.async.cg.shared.global [%0], [%1], 16, %2;"
        :: "r"(d), "l"(s), "r"(bytes));
}
#define CP_COMMIT asm volatile("cp.async.commit_group;")
#define CP_WAIT1  asm volatile("cp.async.wait_group 1;")

// ---------------- depthwise 3x3 conv (SAME) + bias ----------------
__global__ void dw_kernel(const float* __restrict__ x, const float* __restrict__ w,
                          const float* __restrict__ bia, float* __restrict__ out)
{
    int wq = threadIdx.x;
    int hq = blockIdx.y * 4 + threadIdx.y;
    int plane = blockIdx.z;
    int c = plane & (Cc - 1);
    const float* xp = x + (long)plane * HW;
    const float* wp = w + c * 9;
    float w00 = wp[0], w01 = wp[1], w02 = wp[2];
    float w10 = wp[3], w11 = wp[4], w12 = wp[5];
    float w20 = wp[6], w21 = wp[7], w22 = wp[8];
    float acc = bia[c];

    const float* r0 = xp + (hq - 1) * Ww;
    const float* r1 = xp + hq * Ww;
    const float* r2 = xp + (hq + 1) * Ww;
    bool ht = hq > 0, hb = hq < Hh - 1;
    bool wl = wq > 0, wr = wq < Ww - 1;

    if (ht) {
        if (wl) acc += w00 * r0[wq - 1];
        acc += w01 * r0[wq];
        if (wr) acc += w02 * r0[wq + 1];
    }
    {
        if (wl) acc += w10 * r1[wq - 1];
        acc += w11 * r1[wq];
        if (wr) acc += w12 * r1[wq + 1];
    }
    if (hb) {
        if (wl) acc += w20 * r2[wq - 1];
        acc += w21 * r2[wq];
        if (wr) acc += w22 * r2[wq + 1];
    }
    out[(long)plane * HW + hq * Ww + wq] = acc;
}

// ---------------- LN stats + apply + split, [c][pix] planes ----------------
__global__ void stats_kernel(const float* __restrict__ t,
                             const float* __restrict__ lw, const float* __restrict__ lb,
                             __nv_bfloat16* __restrict__ oh, __nv_bfloat16* __restrict__ ol)
{
    int p = blockIdx.x * blockDim.x + threadIdx.x;
    if (p >= Bb*HW) return;
    int bb = p / HW;
    int pix = p - bb * HW;
    const float* base = t + (long)bb * CHW + pix;
    float s = 0.f, s2 = 0.f;
#pragma unroll 8
    for (int c = 0; c < Cc; c++) {
        float v = base[(long)c * HW];
        s += v; s2 += v * v;
    }
    float m = s * (1.0f / Cc);
    float var = s2 * (1.0f / Cc) - m * m;
    float inv = rsqrtf(var + 1e-6f);

    __nv_bfloat16* po = oh + (long)bb * CHW + pix;
    __nv_bfloat16* pl = ol + (long)bb * CHW + pix;
#pragma unroll 4
    for (int c = 0; c < Cc; c++) {
        float v = (base[(long)c * HW] - m) * inv * lw[c] + lb[c];
        __nv_bfloat16 h, l;
        split_bf16(v, h, l);
        po[(long)c * HW] = h;
        pl[(long)c * HW] = l;
    }
}

// ---------------- elementwise split f32 -> bf16 hi/lo ----------------
__global__ void split_k(const float* __restrict__ src,
                        __nv_bfloat16* __restrict__ hi, __nv_bfloat16* __restrict__ lo,
                        int n4)
{
    int i = blockIdx.x * blockDim.x + threadIdx.x;
    if (i >= n4) return;
    float4 v = ((const float4*)src)[i];
    __nv_bfloat16 h0,l0,h1,l1,h2,l2,h3,l3;
    split_bf16(v.x,h0,l0); split_bf16(v.y,h1,l1);
    split_bf16(v.z,h2,l2); split_bf16(v.w,h3,l3);
    ((uint32_t*)hi)[i*2]   = pk2(h0,h1);
    ((uint32_t*)hi)[i*2+1] = pk2(h2,h3);
    ((uint32_t*)lo)[i*2]   = pk2(l0,l1);
    ((uint32_t*)lo)[i*2+1] = pk2(l2,l3);
}

// ---------------- transpose + split ----------------
__global__ void splitT_k(const float* __restrict__ X,
                         __nv_bfloat16* __restrict__ Oh, __nv_bfloat16* __restrict__ Ol,
                         int Krows, int Ncols)
{
    int z = blockIdx.z;
    long zoff = (long)z * Krows * Ncols;
    X += zoff; Oh += zoff; Ol += zoff;

    __shared__ float ts[32][33];
    int n0 = blockIdx.x * 32, k0 = blockIdx.y * 32;
    int tx = threadIdx.x, ty = threadIdx.y;

#pragma unroll
    for (int j = 0; j < 4; j++)
        ts[ty + j*8][tx] = X[(long)(k0 + ty + j*8) * Ncols + n0 + tx];
    __syncthreads();

#pragma unroll
    for (int j = 0; j < 4; j++) {
        int n = n0 + ty + j*8;
        int k = k0 + tx;
        float v = ts[tx][ty + j*8];
        __nv_bfloat16 h, l;
        split_bf16(v, h, l);
        Oh[(long)n * Krows + k] = h;
        Ol[(long)n * Krows + k] = l;
    }
}

// ---------------- bf16 tensor-core GEMM, pre-split streaming ----------------
template<int ACT, int BIASM, bool RES, bool OUTF, bool OUTS>
__global__ void __launch_bounds__(256, 2)
gemm_ps(const __nv_bfloat16* __restrict__ Ah_g, const __nv_bfloat16* __restrict__ Al_g,
        const __nv_bfloat16* __restrict__ Bh_g, const __nv_bfloat16* __restrict__ Bl_g,
        const float* __restrict__ bias, const float* __restrict__ resid,
        float* __restrict__ C, __nv_bfloat16* __restrict__ Oh, __nv_bfloat16* __restrict__ Ol,
        int M, int N, int K, long sA, long sB, long sC)
{
    extern __shared__ __align__(16) char dsm[];
    uint32_t sb = su32(dsm);

    int z = blockIdx.z;
    Ah_g += z * sA; Al_g += z * sA;
    Bh_g += z * sB; Bl_g += z * sB;
    if (OUTF) C += z * sC;
    if (OUTS) { Oh += z * sC; Ol += z * sC; }
    const float* R = RES ? (resid + z * sC) : nullptr;

    int m0 = blockIdx.y * 128;
    int n0 = blockIdx.x * 64;
    int tid = threadIdx.x;
    int warp = tid >> 5;
    int lane = tid & 31;
    int wm = warp & 3;
    int wn = warp >> 2;

    int a_r = tid >> 1;
    int a_c = (tid & 1) * 2;
    int b_r = tid >> 3;
    int b_c = tid & 7;

    const int KT = K >> 5;

    auto loadStage = [&](int st, int kb) {
        uint32_t abase = sb + st * STG_SZ;
        bool mok = (m0 + a_r) < M;
        int ab = mok ? 16 : 0;
        const __nv_bfloat16* sh = Ah_g + (long)(m0 + a_r) * K + kb;
        const __nv_bfloat16* sl = Al_g + (long)(m0 + a_r) * K + kb;
        uint32_t dA = abase + a_r * 80 + a_c * 16;
#pragma unroll
        for (int j = 0; j < 2; j++) {
            cpa16(dA + STG_A_H + j * 16, sh + (a_c + j) * 8, ab);
            cpa16(dA + STG_A_L + j * 16, sl + (a_c + j) * 8, ab);
        }
        const __nv_bfloat16* bh = Bh_g + (long)(kb + b_r) * N + n0 + b_c * 8;
        const __nv_bfloat16* bl = Bl_g + (long)(kb + b_r) * N + n0 + b_c * 8;
        uint32_t dB = abase + b_r * 144 + b_c * 16;
        cpa16(dB + STG_B_H, bh, 16);
        cpa16(dB + STG_B_L, bl, 16);
    };

    loadStage(0, 0);
    CP_COMMIT;
    if (KT > 1) loadStage(1, 32);
    CP_COMMIT;

    float acc[2][4][4];
#pragma unroll
    for (int i = 0; i < 2; i++)
#pragma unroll
        for (int j = 0; j < 4; j++)
#pragma unroll
            for (int q = 0; q < 4; q++) acc[i][j][q] = 0.f;

    int a_mrow = lane & 15;
    int a_kh = (lane >> 4) * 8;
    int bg = lane >> 3;
    int b_kr = (bg & 1) * 8 + (lane & 7);
    int b_nc = (bg >> 1) * 8;

    int st = 0;
    for (int kt = 0; kt < KT; kt++) {
        CP_WAIT1;
        __syncthreads();
        if (kt + 2 < KT) loadStage((st + 2 >= 3) ? st - 1 : st + 2, (kt + 2) << 5);
        CP_COMMIT;

        uint32_t base = sb + st * STG_SZ;
#pragma unroll
        for (int half = 0; half < 2; half++) {
            int kc = half * 16;
            uint32_t afr[2][2][4];
#pragma unroll
            for (int s = 0; s < 2; s++) {
                uint32_t ap = base + (s ? STG_A_L : STG_A_H);
#pragma unroll
                for (int mt = 0; mt < 2; mt++)
                    ldsm4(afr[s][mt], ap + ((wm*32 + mt*16 + a_mrow) * RS + kc + a_kh) * 2);
            }
            uint32_t bfr[2][2][4];
#pragma unroll
            for (int p = 0; p < 2; p++) {
                uint32_t boff = ((kc + b_kr) * RSB + wn*32 + p*16 + b_nc) * 2;
                ldsm4t(bfr[p][0], base + STG_B_H + boff);
                ldsm4t(bfr[p][1], base + STG_B_L + boff);
            }
#pragma unroll
            for (int p = 0; p < 2; p++)
#pragma unroll
                for (int mt = 0; mt < 2; mt++) {
                    mma16816(acc[mt][2*p],   afr[0][mt], bfr[p][0]);
                    mma16816(acc[mt][2*p+1], afr[0][mt], bfr[p][0] + 2);
                }
#pragma unroll
            for (int p = 0; p < 2; p++)
#pragma unroll
                for (int mt = 0; mt < 2; mt++) {
                    mma16816(acc[mt][2*p],   afr[0][mt], bfr[p][1]);
                    mma16816(acc[mt][2*p+1], afr[0][mt], bfr[p][1] + 2);
                }
#pragma unroll
            for (int p = 0; p < 2; p++)
#pragma unroll
                for (int mt = 0; mt < 2; mt++) {
                    mma16816(acc[mt][2*p],   afr[1][mt], bfr[p][0]);
                    mma16816(acc[mt][2*p+1], afr[1][mt], bfr[p][0] + 2);
                }
        }
        st++;
        if (st == 3) st = 0;
    }

    // ---- epilogue ----
#pragma unroll
    for (int mt = 0; mt < 2; mt++) {
#pragma unroll
        for (int nt = 0; nt < 4; nt++) {
            int gn = n0 + wn*32 + nt*8 + (lane & 3) * 2;
            float bn0v = 0.f, bn1v = 0.f;
            if (BIASM == 2) { bn0v = bias[gn]; bn1v = bias[gn + 1]; }
#pragma unroll
            for (int h = 0; h < 2; h++) {
                int row = m0 + wm*32 + mt*16 + (lane >> 2) + h*8;
                if (row >= M) continue;
                float x0 = acc[mt][nt][h*2 + 0];
                float x1 = acc[mt][nt][h*2 + 1];
                if (BIASM == 1) { float bm = bias[row]; x0 += bm; x1 += bm; }
                if (BIASM == 2) { x0 += bn0v; x1 += bn1v; }
                if (ACT == 1) { x0 = fmaxf(x0, 0.f); x1 = fmaxf(x1, 0.f); }
                if (ACT == 2) { x0 = gelu_f(x0); x1 = gelu_f(x1); }
                if (RES) {
                    float2 r2 = *(const float2*)&R[(long)row * N + gn];
                    x0 += r2.x; x1 += r2.y;
                }
                if (OUTF) {
                    float2 o; o.x = x0; o.y = x1;
                    *(float2*)&C[(long)row * N + gn] = o;
                }
                if (OUTS) {
                    __nv_bfloat16 h0, l0, h1, l1;
                    split_bf16(x0, h0, l0);
                    split_bf16(x1, h1, l1);
                    *(uint32_t*)&Oh[(long)row * N + gn] = pk2(h0, h1);
                    *(uint32_t*)&Ol[(long)row * N + gn] = pk2(l0, l1);
                }
            }
        }
    }
}

// ---------------- per-query offset ----------------
__global__ void off_kernel(const float* __restrict__ q4, const float* __restrict__ sb,
                           const float* __restrict__ hb, float* __restrict__ off)
{
    int n = blockIdx.x * blockDim.x + threadIdx.x;
    if (n >= Bb*Nq) return;
    float s = hb[0];
#pragma unroll 8
    for (int i = 0; i < IDim; i++) s += q4[(long)n * IDim + i] * sb[i];
    off[n] = s;
}

// ---------------- bilinear 2x upsample + offset ----------------
__global__ void upsample_kernel(const float* __restrict__ m, const float* __restrict__ off,
                                float* __restrict__ out)
{
    long idx = (long)blockIdx.x * blockDim.x + threadIdx.x;
    const long tot4 = (long)Bb * Nq * H2 * (W2 / 4);
    if (idx >= tot4) return;
    int wq4 = (int)(idx % (W2 / 4)) * 4;
    int h2 = (int)((idx / (W2 / 4)) % H2);
    long bn = idx / ((long)(W2 / 4) * H2);

    float fh = h2 * 0.5f - 0.25f;
    int h0f = (int)floorf(fh);
    float wh = fh - (float)h0f;
    int h0 = max(h0f, 0), h1 = min(h0f + 1, Hh - 1);

    const float* r0 = m + bn * (long)HW + h0 * Ww;
    const float* r1 = m + bn * (long)HW + h1 * Ww;
    float o = off[bn];

    float r[4];
#pragma unroll
    for (int j = 0; j < 4; j++) {
        int w2 = wq4 + j;
        float fw = w2 * 0.5f - 0.25f;
        int w0f = (int)floorf(fw);
        float ww = fw - (float)w0f;
        int w0 = max(w0f, 0), w1 = min(w0f + 1, Ww - 1);
        float t0 = r0[w0] * (1.f - ww) + r0[w1] * ww;
        float t1 = r1[w0] * (1.f - ww) + r1[w1] * ww;
        r[j] = t0 * (1.f - wh) + t1 * wh + o;
    }
    float4 v = make_float4(r[0], r[1], r[2], r[3]);
    *(float4*)(out + bn * (long)(H2 * W2) + (long)h2 * W2 + wq4) = v;
}

// ---------------- launcher ----------------
extern "C" void kernel_launch(void* const* d_in, const int* in_sizes, int n_in,
                              void* d_out, int out_size)
{
    const float* spat    = (const float*)d_in[0];
    const float* qf      = (const float*)d_in[1];
    const float* dw_w    = (const float*)d_in[2];
    const float* dw_b    = (const float*)d_in[3];
    const float* ln_w    = (const float*)d_in[4];
    const float* ln_b    = (const float*)d_in[5];
    const float* pw_w    = (const float*)d_in[6];
    const float* pw_b    = (const float*)d_in[7];
    const float* sproj_w = (const float*)d_in[8];
    const float* sproj_b = (const float*)d_in[9];
    const float* mlp_w1  = (const float*)d_in[10];
    const float* mlp_b1  = (const float*)d_in[11];
    const float* mlp_w2  = (const float*)d_in[12];
    const float* mlp_b2  = (const float*)d_in[13];
    const float* mlp_w3  = (const float*)d_in[14];
    const float* mlp_b3  = (const float*)d_in[15];
    const float* qproj_w = (const float*)d_in[16];
    const float* qproj_b = (const float*)d_in[17];
    const float* head_b  = (const float*)d_in[18];
    float* out = (float*)d_out;

    float *px, *pt, *pq4, *poff, *pm;
    cudaGetSymbolAddress((void**)&px,   g_x);
    cudaGetSymbolAddress((void**)&pt,   g_t);
    cudaGetSymbolAddress((void**)&pq4,  g_q4);
    cudaGetSymbolAddress((void**)&poff, g_off);
    cudaGetSymbolAddress((void**)&pm,   g_m);

    __nv_bfloat16 *pwh,*pwl,*w1h,*w1l,*w2h,*w2l,*w3h,*w3l,*qph,*qpl,*sph,*spl;
    __nv_bfloat16 *qfh,*qfl,*o1h,*o1l,*o2h,*o2l,*o3h,*o3l,*o4h,*o4l,*qqh,*qql,*bsh,*bsl,*ysh,*ysl;
    cudaGetSymbolAddress((void**)&pwh, g_pwh); cudaGetSymbolAddress((void**)&pwl, g_pwl);
    cudaGetSymbolAddress((void**)&w1h, g_w1h); cudaGetSymbolAddress((void**)&w1l, g_w1l);
    cudaGetSymbolAddress((void**)&w2h, g_w2h); cudaGetSymbolAddress((void**)&w2l, g_w2l);
    cudaGetSymbolAddress((void**)&w3h, g_w3h); cudaGetSymbolAddress((void**)&w3l, g_w3l);
    cudaGetSymbolAddress((void**)&qph, g_qph); cudaGetSymbolAddress((void**)&qpl, g_qpl);
    cudaGetSymbolAddress((void**)&sph, g_sph); cudaGetSymbolAddress((void**)&spl, g_spl);
    cudaGetSymbolAddress((void**)&qfh, g_qfh); cudaGetSymbolAddress((void**)&qfl, g_qfl);
    cudaGetSymbolAddress((void**)&o1h, g_o1h); cudaGetSymbolAddress((void**)&o1l, g_o1l);
    cudaGetSymbolAddress((void**)&o2h, g_o2h); cudaGetSymbolAddress((void**)&o2l, g_o2l);
    cudaGetSymbolAddress((void**)&o3h, g_o3h); cudaGetSymbolAddress((void**)&o3l, g_o3l);
    cudaGetSymbolAddress((void**)&o4h, g_o4h); cudaGetSymbolAddress((void**)&o4l, g_o4l);
    cudaGetSymbolAddress((void**)&qqh, g_qqh); cudaGetSymbolAddress((void**)&qql, g_qql);
    cudaGetSymbolAddress((void**)&bsh, g_bsh); cudaGetSymbolAddress((void**)&bsl, g_bsl);
    cudaGetSymbolAddress((void**)&ysh, g_ysh); cudaGetSymbolAddress((void**)&ysl, g_ysl);

    cudaFuncSetAttribute(gemm_ps<1,2,false,false,true>,  cudaFuncAttributeMaxDynamicSharedMemorySize, SMEMB);
    cudaFuncSetAttribute(gemm_ps<2,1,true,true,false>,   cudaFuncAttributeMaxDynamicSharedMemorySize, SMEMB);
    cudaFuncSetAttribute(gemm_ps<2,1,true,false,true>,   cudaFuncAttributeMaxDynamicSharedMemorySize, SMEMB);
    cudaFuncSetAttribute(gemm_ps<0,2,false,false,true>,  cudaFuncAttributeMaxDynamicSharedMemorySize, SMEMB);
    cudaFuncSetAttribute(gemm_ps<0,2,false,true,true>,   cudaFuncAttributeMaxDynamicSharedMemorySize, SMEMB);
    cudaFuncSetAttribute(gemm_ps<0,0,false,false,true>,  cudaFuncAttributeMaxDynamicSharedMemorySize, SMEMB);
    cudaFuncSetAttribute(gemm_ps<0,0,false,true,false>,  cudaFuncAttributeMaxDynamicSharedMemorySize, SMEMB);

    dim3 dwBlock(80, 4);
    dim3 dwGrid(1, Hh / 4, Bb * Cc);
    dim3 tBlock(32, 8);
    const int pix = Bb * HW;
    const int Mq = Bb * Nq;

    // ---- fork a side stream for the query chain (capture-legal fork/join) ----
    cudaStream_t s1;
    cudaStreamCreateWithFlags(&s1, cudaStreamNonBlocking);
    cudaEvent_t evFork, evJoin;
    cudaEventCreateWithFlags(&evFork, cudaEventDisableTiming);
    cudaEventCreateWithFlags(&evJoin, cudaEventDisableTiming);
    cudaEventRecord(evFork, 0);
    cudaStreamWaitEvent(s1, evFork, 0);

    // ======== side stream s1: full query chain ========
    split_k<<<(Mq*Cc/4 + 255)/256, 256, 0, s1>>>(qf, qfh, qfl, Mq*Cc/4);
    splitT_k<<<dim3(Cc/32, HID/32, 1), tBlock, 0, s1>>>(mlp_w1, w1h, w1l, HID, Cc);
    splitT_k<<<dim3(HID/32, HID/32, 1), tBlock, 0, s1>>>(mlp_w2, w2h, w2l, HID, HID);
    splitT_k<<<dim3(HID/32, Cc/32, 1), tBlock, 0, s1>>>(mlp_w3, w3h, w3l, Cc, HID);
    splitT_k<<<dim3(Cc/32, IDim/32, 1), tBlock, 0, s1>>>(qproj_w, qph, qpl, IDim, Cc);
    split_k<<<(IDim*Cc/4 + 255)/256, 256, 0, s1>>>(sproj_w, sph, spl, IDim*Cc/4);

    gemm_ps<1, 2, false, false, true><<<dim3(HID/64, 10, 1), 256, SMEMB, s1>>>(
        qfh, qfl, w1h, w1l, mlp_b1, nullptr, nullptr, o1h, o1l,
        Mq, HID, Cc, 0, 0, 0);
    gemm_ps<1, 2, false, false, true><<<dim3(HID/64, 10, 1), 256, SMEMB, s1>>>(
        o1h, o1l, w2h, w2l, mlp_b2, nullptr, nullptr, o2h, o2l,
        Mq, HID, HID, 0, 0, 0);
    gemm_ps<0, 2, false, false, true><<<dim3(Cc/64, 10, 1), 256, SMEMB, s1>>>(
        o2h, o2l, w3h, w3l, mlp_b3, nullptr, nullptr, o3h, o3l,
        Mq, Cc, HID, 0, 0, 0);
    gemm_ps<0, 2, false, true, true><<<dim3(IDim/64, 10, 1), 256, SMEMB, s1>>>(
        o3h, o3l, qph, qpl, qproj_b, nullptr, pq4, o4h, o4l,
        Mq, IDim, Cc, 0, 0, 0);
    gemm_ps<0, 0, false, false, true><<<dim3(Cc/64, 10, 1), 256, SMEMB, s1>>>(
        o4h, o4l, sph, spl, nullptr, nullptr, nullptr, qqh, qql,
        Mq, Cc, IDim, 0, 0, 0);
    off_kernel<<<(Mq + 255)/256, 256, 0, s1>>>(pq4, sproj_b, head_b, poff);
    cudaEventRecord(evJoin, s1);

    // ======== main stream: spatial path ========
    split_k<<<(2*Cc*Cc/4 + 255)/256, 256>>>(pw_w, pwh, pwl, 2*Cc*Cc/4);
    dw_kernel<<<dwGrid, dwBlock>>>(spat, dw_w, dw_b, pt);
    stats_kernel<<<(pix + 255)/256, 256>>>(pt, ln_w, ln_b, bsh, bsl);
    gemm_ps<2, 1, true, true, false><<<dim3(HW/64, 2, Bb), 256, SMEMB>>>(
        pwh, pwl, bsh, bsl, pw_b, spat, px, nullptr, nullptr,
        Cc, HW, Cc, 0, (long)CHW, (long)CHW);

    dw_kernel<<<dwGrid, dwBlock>>>(px, dw_w + Cc*9, dw_b + Cc, pt);
    stats_kernel<<<(pix + 255)/256, 256>>>(pt, ln_w + Cc, ln_b + Cc, bsh, bsl);
    gemm_ps<2, 1, true, false, true><<<dim3(HW/64, 2, Bb), 256, SMEMB>>>(
        pwh + Cc*Cc, pwl + Cc*Cc, bsh, bsl, pw_b + Cc, px, nullptr, ysh, ysl,
        Cc, HW, Cc, 0, (long)CHW, (long)CHW);

    // ---- join: mask GEMM needs query chain results ----
    cudaStreamWaitEvent(0, evJoin, 0);

    gemm_ps<0, 0, false, true, false><<<dim3(HW/64, 3, Bb), 256, SMEMB>>>(
        qqh, qql, ysh, ysl, nullptr, nullptr, pm, nullptr, nullptr,
        Nq, HW, Cc, (long)Nq*Cc, (long)CHW, (long)Nq*HW);

    const long tot4 = (long)Bb * Nq * H2 * (W2 / 4);
    upsample_kernel<<<(unsigned)((tot4 + 255)/256), 256>>>(pm, poff, out);
}